// round 11
// baseline (speedup 1.0000x reference)
#include <cuda_runtime.h>
#include <math.h>
#include <stdint.h>

#define S_LEN 2048
#define BATCH 2
#define EMB   1024
#define NH    16
#define HD    64
#define HID   512
#define MROWS (S_LEN*BATCH)   // 4096
#define HSZ   (BATCH*NH*S_LEN*HD)
#define LOG2E 1.4426950408889634f

// ---------------- scratch (static device globals; no allocation) ----------
__device__ float g_qkv[3*HSZ];               // q|k|v in (B,H,S,D), tf32-rounded
__device__ float g_ctx[MROWS*EMB];           // (S,B,E) tf32-rounded
__device__ float g_t1 [MROWS*HID];
__device__ float g_mcomb[NH*HID];
__device__ float g_cbias[NH];
__device__ float g_mask[BATCH*NH*S_LEN];
__device__ float g_qr [MROWS*EMB];           // tf32-rounded query
__device__ float g_wqkv[3*EMB*EMB];          // tf32-rounded q_w|k_w|v_w
__device__ float g_wo [EMB*EMB];             // tf32-rounded out_w

// =================== helpers ===============================================
__device__ __forceinline__ uint32_t f2tf(float x) {
    uint32_t r; asm("cvt.rna.tf32.f32 %0, %1;" : "=r"(r) : "f"(x)); return r;
}
__device__ __forceinline__ float rtf(float x) { return __uint_as_float(f2tf(x)); }
__device__ __forceinline__ uint32_t smem_u32(const void* p) {
    uint32_t a;
    asm("{ .reg .u64 t; cvta.to.shared.u64 t, %1; cvt.u32.u64 %0, t; }"
        : "=r"(a) : "l"(p));
    return a;
}
__device__ __forceinline__ void cp16(uint32_t saddr, const void* g) {
    asm volatile("cp.async.cg.shared.global [%0], [%1], 16;"
                 :: "r"(saddr), "l"(g) : "memory");
}
__device__ __forceinline__ void mma_tf32(float* d, const uint32_t* a, const uint32_t* b) {
    asm volatile(
        "mma.sync.aligned.m16n8k8.row.col.f32.tf32.tf32.f32 "
        "{%0,%1,%2,%3}, {%4,%5,%6,%7}, {%8,%9}, {%0,%1,%2,%3};"
        : "+f"(d[0]), "+f"(d[1]), "+f"(d[2]), "+f"(d[3])
        : "r"(a[0]), "r"(a[1]), "r"(a[2]), "r"(a[3]), "r"(b[0]), "r"(b[1]));
}

// ---------------- fused tf32 rounding of query + 4 weight matrices --------
#define NQ4 (MROWS*EMB/4)      // 1048576
#define NW4 (EMB*EMB/4)        // 262144 = 1<<18
__global__ void round_all(const float* __restrict__ q,
                          const float* __restrict__ wq,
                          const float* __restrict__ wk,
                          const float* __restrict__ wv,
                          const float* __restrict__ wo,
                          float* __restrict__ dq,
                          float* __restrict__ dwqkv,
                          float* __restrict__ dwo)
{
    const int i = blockIdx.x * blockDim.x + threadIdx.x;
    const float4* src; float4* dst; int off;
    if (i < NQ4) { src = (const float4*)q; dst = (float4*)dq; off = i; }
    else {
        const int j = i - NQ4;
        const int z = j >> 18;
        off = j & (NW4 - 1);
        if      (z == 0) { src = (const float4*)wq; dst = (float4*)dwqkv; }
        else if (z == 1) { src = (const float4*)wk; dst = (float4*)dwqkv + NW4; }
        else if (z == 2) { src = (const float4*)wv; dst = (float4*)dwqkv + 2*NW4; }
        else             { src = (const float4*)wo; dst = (float4*)dwo; }
    }
    float4 v = src[off];
    v.x = rtf(v.x); v.y = rtf(v.y); v.z = rtf(v.z); v.w = rtf(v.w);
    dst[off] = v;
}

// =================== cp.async pipelined tf32 GEMM core (k-permuted) ========
#define GEMM_BODY(Ag, Wg)                                                      \
    float acc[4][4][4];                                                        \
    _Pragma("unroll")                                                          \
    for (int i = 0; i < 4; i++)                                                \
        _Pragma("unroll")                                                      \
        for (int j = 0; j < 4; j++)                                            \
            _Pragma("unroll")                                                  \
            for (int f = 0; f < 4; f++) acc[i][j][f] = 0.f;                    \
    const int NC = K >> 5;                                                     \
    const int r0 = tid >> 3;                                                   \
    const int sg = tid & 7;                                                    \
    {                                                                          \
        const uint32_t ab = sbase, wb = sbase + 5120u * 4u;                    \
        _Pragma("unroll")                                                      \
        for (int i = 0; i < 4; i++) {                                          \
            const int row = r0 + i * 32;                                       \
            const uint32_t off = (uint32_t)(row * 40 + sg * 4) * 4u;           \
            cp16(ab + off, Ag + (size_t)row * K + sg * 4);                     \
            cp16(wb + off, Wg + (size_t)row * K + sg * 4);                     \
        }                                                                      \
        asm volatile("cp.async.commit_group;" ::: "memory");                   \
    }                                                                          \
    for (int c = 0; c < NC; c++) {                                             \
        if (c + 1 < NC) {                                                      \
            const uint32_t st = (uint32_t)((c + 1) & 1) * 10240u * 4u;         \
            const uint32_t ab = sbase + st, wb = sbase + st + 5120u * 4u;      \
            const int kn = (c + 1) << 5;                                       \
            _Pragma("unroll")                                                  \
            for (int i = 0; i < 4; i++) {                                      \
                const int row = r0 + i * 32;                                   \
                const uint32_t off = (uint32_t)(row * 40 + sg * 4) * 4u;       \
                cp16(ab + off, Ag + (size_t)row * K + kn + sg * 4);            \
                cp16(wb + off, Wg + (size_t)row * K + kn + sg * 4);            \
            }                                                                  \
            asm volatile("cp.async.commit_group;" ::: "memory");               \
            asm volatile("cp.async.wait_group 1;" ::: "memory");               \
        } else {                                                               \
            asm volatile("cp.async.wait_group 0;" ::: "memory");               \
        }                                                                      \
        __syncthreads();                                                       \
        const uint32_t* As = sw + (c & 1) * 10240;                             \
        const uint32_t* Ws = As + 5120;                                        \
        _Pragma("unroll")                                                      \
        for (int ks = 0; ks < 4; ks++) {                                       \
            const int k0 = ks * 8;                                             \
            uint32_t af[4][4];                                                 \
            _Pragma("unroll")                                                  \
            for (int mt = 0; mt < 4; mt++) {                                   \
                const int r = wm * 64 + mt * 16 + gid;                         \
                uint2 a0 = *(const uint2*)&As[ r      * 40 + k0 + 2 * tig];    \
                uint2 a1 = *(const uint2*)&As[(r + 8) * 40 + k0 + 2 * tig];    \
                af[mt][0] = a0.x; af[mt][1] = a1.x;                            \
                af[mt][2] = a0.y; af[mt][3] = a1.y;                            \
            }                                                                  \
            uint32_t bf[4][2];                                                 \
            _Pragma("unroll")                                                  \
            for (int nt = 0; nt < 4; nt++) {                                   \
                const int n = wn * 32 + nt * 8 + gid;                          \
                uint2 w = *(const uint2*)&Ws[n * 40 + k0 + 2 * tig];           \
                bf[nt][0] = w.x; bf[nt][1] = w.y;                              \
            }                                                                  \
            _Pragma("unroll")                                                  \
            for (int mt = 0; mt < 4; mt++)                                     \
                _Pragma("unroll")                                              \
                for (int nt = 0; nt < 4; nt++)                                 \
                    mma_tf32(acc[mt][nt], af[mt], bf[nt]);                     \
        }                                                                      \
        __syncthreads();                                                       \
    }

// ---- fused QKV projection (Q pre-scaled by 0.125*log2e for exp2 softmax) --
__global__ __launch_bounds__(256, 2)
void mgemm_qkv(const float* __restrict__ A, const float* __restrict__ Wall,
               const float* __restrict__ bq, const float* __restrict__ bk,
               const float* __restrict__ bv, float* __restrict__ Call, int K)
{
    extern __shared__ uint32_t sw[];
    const uint32_t sbase = smem_u32(sw);
    const int tid  = threadIdx.x;
    const int wid  = tid >> 5;
    const int lane = tid & 31;
    const int gid  = lane >> 2;
    const int tig  = lane & 3;
    const int wm   = wid >> 2;
    const int wn   = wid & 3;
    const int z    = blockIdx.z;

    const float* Ag = A + (size_t)blockIdx.y * 128 * K;
    const float* Wg = Wall + (size_t)z * EMB * EMB + (size_t)blockIdx.x * 128 * K;
    const float* bias = (z == 0) ? bq : (z == 1) ? bk : bv;
    float* C = Call + (size_t)z * HSZ;
    const float scale = (z == 0) ? 0.125f * LOG2E : 1.f;

    GEMM_BODY(Ag, Wg)

    #pragma unroll
    for (int mt = 0; mt < 4; mt++) {
        #pragma unroll
        for (int nt = 0; nt < 4; nt++) {
            const int n = blockIdx.x * 128 + wn * 32 + nt * 8 + tig * 2;
            const float b0 = bias[n], b1 = bias[n + 1];
            #pragma unroll
            for (int half = 0; half < 2; half++) {
                const int m = blockIdx.y * 128 + wm * 64 + mt * 16 + gid + half * 8;
                float2 v;
                v.x = rtf((acc[mt][nt][half * 2 + 0] + b0) * scale);
                v.y = rtf((acc[mt][nt][half * 2 + 1] + b1) * scale);
                const int s = m >> 1, b = m & 1;
                const int h = n >> 6, d = n & 63;
                *(float2*)(C + (((size_t)(b * NH + h)) * S_LEN + s) * HD + d) = v;
            }
        }
    }
}

// ---- output projection (m_base selects row half) ---------------------------
__global__ __launch_bounds__(256, 2)
void mgemm_out(const float* __restrict__ A, const float* __restrict__ W,
               const float* __restrict__ bias, float* __restrict__ C, int K,
               int m_base)
{
    extern __shared__ uint32_t sw[];
    const uint32_t sbase = smem_u32(sw);
    const int tid  = threadIdx.x;
    const int wid  = tid >> 5;
    const int lane = tid & 31;
    const int gid  = lane >> 2;
    const int tig  = lane & 3;
    const int wm   = wid >> 2;
    const int wn   = wid & 3;

    const float* Ag = A + ((size_t)m_base + (size_t)blockIdx.y * 128) * K;
    const float* Wg = W + (size_t)blockIdx.x * 128 * K;

    GEMM_BODY(Ag, Wg)

    #pragma unroll
    for (int mt = 0; mt < 4; mt++) {
        #pragma unroll
        for (int nt = 0; nt < 4; nt++) {
            const int n = blockIdx.x * 128 + wn * 32 + nt * 8 + tig * 2;
            const float b0 = bias[n], b1 = bias[n + 1];
            #pragma unroll
            for (int half = 0; half < 2; half++) {
                const int m = m_base + blockIdx.y * 128 + wm * 64 + mt * 16 + gid + half * 8;
                float2 v;
                v.x = acc[mt][nt][half * 2 + 0] + b0;
                v.y = acc[mt][nt][half * 2 + 1] + b1;
                *(float2*)(C + (size_t)m * (gridDim.x * 128) + n) = v;
            }
        }
    }
}

// =================== split-tf32 (3xMMA) GEMM + ReLU for the mask MLP =======
__global__ __launch_bounds__(256)
void mgemm_3x_relu(const float* __restrict__ A, const float* __restrict__ W,
                   const float* __restrict__ bias, float* __restrict__ C, int K)
{
    extern __shared__ uint32_t sw[];
    const uint32_t sbase = smem_u32(sw);
    const float* swf = (const float*)sw;
    const int tid  = threadIdx.x;
    const int wid  = tid >> 5;
    const int lane = tid & 31;
    const int gid  = lane >> 2;
    const int tig  = lane & 3;
    const int wm   = wid >> 2;
    const int wn   = wid & 3;

    const float* Ag = A + (size_t)blockIdx.y * 128 * K;
    const float* Wg = W + (size_t)blockIdx.x * 128 * K;

    float acc[4][4][4];
    #pragma unroll
    for (int i = 0; i < 4; i++)
        #pragma unroll
        for (int j = 0; j < 4; j++)
            #pragma unroll
            for (int f = 0; f < 4; f++) acc[i][j][f] = 0.f;

    const int NC = K >> 5;
    const int r0 = tid >> 3;
    const int sg = tid & 7;

    {
        const uint32_t ab = sbase, wb = sbase + 4608u * 4u;
        #pragma unroll
        for (int i = 0; i < 4; i++) {
            const int row = r0 + i * 32;
            const uint32_t off = (uint32_t)(row * 36 + sg * 4) * 4u;
            cp16(ab + off, Ag + (size_t)row * K + sg * 4);
            cp16(wb + off, Wg + (size_t)row * K + sg * 4);
        }
        asm volatile("cp.async.commit_group;" ::: "memory");
    }

    for (int c = 0; c < NC; c++) {
        if (c + 1 < NC) {
            const uint32_t st = (uint32_t)((c + 1) & 1) * 9216u * 4u;
            const uint32_t ab = sbase + st, wb = sbase + st + 4608u * 4u;
            const int kn = (c + 1) << 5;
            #pragma unroll
            for (int i = 0; i < 4; i++) {
                const int row = r0 + i * 32;
                const uint32_t off = (uint32_t)(row * 36 + sg * 4) * 4u;
                cp16(ab + off, Ag + (size_t)row * K + kn + sg * 4);
                cp16(wb + off, Wg + (size_t)row * K + kn + sg * 4);
            }
            asm volatile("cp.async.commit_group;" ::: "memory");
            asm volatile("cp.async.wait_group 1;" ::: "memory");
        } else {
            asm volatile("cp.async.wait_group 0;" ::: "memory");
        }
        __syncthreads();

        const float* As = swf + (c & 1) * 9216;
        const float* Ws = As + 4608;
        #pragma unroll
        for (int ks = 0; ks < 4; ks++) {
            const int k0 = ks * 8;
            uint32_t ah[4][4], al[4][4];
            #pragma unroll
            for (int mt = 0; mt < 4; mt++) {
                const int r = wm * 64 + mt * 16 + gid;
                float a0 = As[ r      * 36 + k0 + tig    ];
                float a1 = As[(r + 8) * 36 + k0 + tig    ];
                float a2 = As[ r      * 36 + k0 + tig + 4];
                float a3 = As[(r + 8) * 36 + k0 + tig + 4];
                ah[mt][0] = f2tf(a0); al[mt][0] = f2tf(a0 - __uint_as_float(ah[mt][0]));
                ah[mt][1] = f2tf(a1); al[mt][1] = f2tf(a1 - __uint_as_float(ah[mt][1]));
                ah[mt][2] = f2tf(a2); al[mt][2] = f2tf(a2 - __uint_as_float(ah[mt][2]));
                ah[mt][3] = f2tf(a3); al[mt][3] = f2tf(a3 - __uint_as_float(ah[mt][3]));
            }
            uint32_t bh_[4][2], bl_[4][2];
            #pragma unroll
            for (int nt = 0; nt < 4; nt++) {
                const int n = wn * 32 + nt * 8 + gid;
                float b0 = Ws[n * 36 + k0 + tig    ];
                float b1 = Ws[n * 36 + k0 + tig + 4];
                bh_[nt][0] = f2tf(b0); bl_[nt][0] = f2tf(b0 - __uint_as_float(bh_[nt][0]));
                bh_[nt][1] = f2tf(b1); bl_[nt][1] = f2tf(b1 - __uint_as_float(bh_[nt][1]));
            }
            #pragma unroll
            for (int mt = 0; mt < 4; mt++)
                #pragma unroll
                for (int nt = 0; nt < 4; nt++) {
                    mma_tf32(acc[mt][nt], al[mt], bh_[nt]);
                    mma_tf32(acc[mt][nt], ah[mt], bl_[nt]);
                    mma_tf32(acc[mt][nt], ah[mt], bh_[nt]);
                }
        }
        __syncthreads();
    }

    #pragma unroll
    for (int mt = 0; mt < 4; mt++) {
        #pragma unroll
        for (int nt = 0; nt < 4; nt++) {
            const int n = blockIdx.x * 128 + wn * 32 + nt * 8 + tig * 2;
            const float b0 = bias[n], b1 = bias[n + 1];
            #pragma unroll
            for (int half = 0; half < 2; half++) {
                const int m = blockIdx.y * 128 + wm * 64 + mt * 16 + gid + half * 8;
                float2 v;
                v.x = fmaxf(acc[mt][nt][half * 2 + 0] + b0, 0.f);
                v.y = fmaxf(acc[mt][nt][half * 2 + 1] + b1, 0.f);
                *(float2*)(C + (size_t)m * (gridDim.x * 128) + n) = v;
            }
        }
    }
}

// =================== tensor-core flash attention (k-permuted, exp2) ========
// q_base selects the s-half this launch covers (grid.x = 8 tiles of 128).
__global__ __launch_bounds__(256, 2)
void flash_tc(const float* __restrict__ Q, const float* __restrict__ Kg,
              const float* __restrict__ Vg, const float* __restrict__ gate,
              float* __restrict__ ctx, int q_base)
{
    extern __shared__ uint32_t sw[];
    const uint32_t sbase = smem_u32(sw);
    const int tid  = threadIdx.x;
    const int wid  = tid >> 5;
    const int lane = tid & 31;
    const int gid  = lane >> 2;
    const int tig  = lane & 3;
    const int bh   = blockIdx.y;
    const int b    = bh >> 4, h = bh & 15;
    const int q0   = q_base + blockIdx.x * 128;

    const float* Qt = Q  + ((size_t)bh * S_LEN + q0) * HD;
    const float* Kb = Kg + (size_t)bh * S_LEN * HD;
    const float* Vb = Vg + (size_t)bh * S_LEN * HD;

    #pragma unroll
    for (int i = 0; i < 8; i++) {
        const int fi = tid + i * 256;
        const int r = fi >> 4, c4 = (fi & 15) * 4;
        float4 v = *(const float4*)(Qt + r * 64 + c4);
        uint32_t* d = &sw[r * 72 + c4];
        d[0] = __float_as_uint(v.x); d[1] = __float_as_uint(v.y);
        d[2] = __float_as_uint(v.z); d[3] = __float_as_uint(v.w);
    }
    __syncthreads();
    uint32_t qa[8][4];
    {
        const int r0q = wid * 16 + gid;
        #pragma unroll
        for (int ks = 0; ks < 8; ks++) {
            uint2 t0 = *(const uint2*)&sw[ r0q      * 72 + ks * 8 + 2 * tig];
            uint2 t1 = *(const uint2*)&sw[(r0q + 8) * 72 + ks * 8 + 2 * tig];
            qa[ks][0] = t0.x; qa[ks][1] = t1.x;
            qa[ks][2] = t0.y; qa[ks][3] = t1.y;
        }
    }
    __syncthreads();

    #pragma unroll 1
    for (int t = 0; t < 2; t++) {
        const uint32_t kb = sbase + (uint32_t)t * 8960u * 4u;
        const uint32_t vb = kb + 4608u * 4u;
        const float* Ksrc = Kb + (size_t)t * 64 * 64;
        const float* Vsrc = Vb + (size_t)t * 64 * 64;
        #pragma unroll
        for (int i = 0; i < 4; i++) {
            const int fi = tid + i * 256;
            const int r = fi >> 4, c4 = (fi & 15) * 4;
            cp16(kb + (uint32_t)(r * 72 + c4) * 4u, Ksrc + r * 64 + c4);
            cp16(vb + (uint32_t)(r * 68 + c4) * 4u, Vsrc + r * 64 + c4);
        }
        asm volatile("cp.async.commit_group;" ::: "memory");
    }

    float miA = -INFINITY, miB = -INFINITY, liA = 0.f, liB = 0.f;
    float oa[8][4];
    #pragma unroll
    for (int nt = 0; nt < 8; nt++)
        #pragma unroll
        for (int f = 0; f < 4; f++) oa[nt][f] = 0.f;

    const int NT = S_LEN / 64;
    for (int t = 0; t < NT; t++) {
        if (t < NT - 2) asm volatile("cp.async.wait_group 1;" ::: "memory");
        else            asm volatile("cp.async.wait_group 0;" ::: "memory");
        __syncthreads();
        const uint32_t* Ks = sw + (t & 1) * 8960;
        const uint32_t* Vs = Ks + 4608;

        float sa[8][4];
        #pragma unroll
        for (int nt = 0; nt < 8; nt++)
            #pragma unroll
            for (int f = 0; f < 4; f++) sa[nt][f] = 0.f;
        #pragma unroll
        for (int ks = 0; ks < 8; ks++) {
            #pragma unroll
            for (int nt = 0; nt < 8; nt++) {
                uint2 u = *(const uint2*)&Ks[(nt * 8 + gid) * 72 + ks * 8 + 2 * tig];
                uint32_t bf[2] = { u.x, u.y };
                mma_tf32(sa[nt], qa[ks], bf);
            }
        }

        float rmA = -INFINITY, rmB = -INFINITY;
        #pragma unroll
        for (int nt = 0; nt < 8; nt++) {
            rmA = fmaxf(rmA, fmaxf(sa[nt][0], sa[nt][1]));
            rmB = fmaxf(rmB, fmaxf(sa[nt][2], sa[nt][3]));
        }
        rmA = fmaxf(rmA, __shfl_xor_sync(0xffffffffu, rmA, 1));
        rmA = fmaxf(rmA, __shfl_xor_sync(0xffffffffu, rmA, 2));
        rmB = fmaxf(rmB, __shfl_xor_sync(0xffffffffu, rmB, 1));
        rmB = fmaxf(rmB, __shfl_xor_sync(0xffffffffu, rmB, 2));

        const float mAn = fmaxf(miA, rmA);
        const float mBn = fmaxf(miB, rmB);
        const float aA  = exp2f(miA - mAn);
        const float aB  = exp2f(miB - mBn);
        miA = mAn; miB = mBn;

        float rsA = 0.f, rsB = 0.f;
        #pragma unroll
        for (int nt = 0; nt < 8; nt++) {
            const float p0 = exp2f(sa[nt][0] - mAn);
            const float p1 = exp2f(sa[nt][1] - mAn);
            const float p2 = exp2f(sa[nt][2] - mBn);
            const float p3 = exp2f(sa[nt][3] - mBn);
            rsA += p0 + p1; rsB += p2 + p3;
            sa[nt][0] = __uint_as_float(f2tf(p0));
            sa[nt][1] = __uint_as_float(f2tf(p1));
            sa[nt][2] = __uint_as_float(f2tf(p2));
            sa[nt][3] = __uint_as_float(f2tf(p3));
        }
        rsA += __shfl_xor_sync(0xffffffffu, rsA, 1);
        rsA += __shfl_xor_sync(0xffffffffu, rsA, 2);
        rsB += __shfl_xor_sync(0xffffffffu, rsB, 1);
        rsB += __shfl_xor_sync(0xffffffffu, rsB, 2);
        liA = liA * aA + rsA;
        liB = liB * aB + rsB;
        #pragma unroll
        for (int nt = 0; nt < 8; nt++) {
            oa[nt][0] *= aA; oa[nt][1] *= aA;
            oa[nt][2] *= aB; oa[nt][3] *= aB;
        }

        #pragma unroll
        for (int ks = 0; ks < 8; ks++) {
            uint32_t af[4];
            af[0] = __float_as_uint(sa[ks][0]);
            af[1] = __float_as_uint(sa[ks][2]);
            af[2] = __float_as_uint(sa[ks][1]);
            af[3] = __float_as_uint(sa[ks][3]);
            #pragma unroll
            for (int nt = 0; nt < 8; nt++) {
                uint32_t bf[2];
                bf[0] = Vs[(ks * 8 + 2 * tig    ) * 68 + nt * 8 + gid];
                bf[1] = Vs[(ks * 8 + 2 * tig + 1) * 68 + nt * 8 + gid];
                mma_tf32(oa[nt], af, bf);
            }
        }
        __syncthreads();

        if (t + 2 < NT) {
            const uint32_t kb = sbase + (uint32_t)(t & 1) * 8960u * 4u;
            const uint32_t vb = kb + 4608u * 4u;
            const float* Ksrc = Kb + (size_t)(t + 2) * 64 * 64;
            const float* Vsrc = Vb + (size_t)(t + 2) * 64 * 64;
            #pragma unroll
            for (int i = 0; i < 4; i++) {
                const int fi = tid + i * 256;
                const int r = fi >> 4, c4 = (fi & 15) * 4;
                cp16(kb + (uint32_t)(r * 72 + c4) * 4u, Ksrc + r * 64 + c4);
                cp16(vb + (uint32_t)(r * 68 + c4) * 4u, Vsrc + r * 64 + c4);
            }
            asm volatile("cp.async.commit_group;" ::: "memory");
        }
    }

    const int sA = q0 + wid * 16 + gid;
    const int sB = sA + 8;
    const float gA = gate[(size_t)bh * S_LEN + sA];
    const float gB = gate[(size_t)bh * S_LEN + sB];
    const float invA = gA / liA;
    const float invB = gB / liB;
    #pragma unroll
    for (int nt = 0; nt < 8; nt++) {
        const int col = h * 64 + nt * 8 + tig * 2;
        float2 va = { rtf(oa[nt][0] * invA), rtf(oa[nt][1] * invA) };
        float2 vb = { rtf(oa[nt][2] * invB), rtf(oa[nt][3] * invB) };
        *(float2*)(ctx + ((size_t)sA * BATCH + b) * EMB + col) = va;
        *(float2*)(ctx + ((size_t)sB * BATCH + b) * EMB + col) = vb;
    }
}

// ---------------- fold head_sig into inf2 ---------------------------------
__global__ void combine_sig(const float* __restrict__ hs,
                            const float* __restrict__ w2,
                            const float* __restrict__ b2,
                            float* __restrict__ mcomb,
                            float* __restrict__ cbias)
{
    const int idx = blockIdx.x * blockDim.x + threadIdx.x;
    if (idx < NH * HID) {
        const int h = idx / HID, k = idx % HID;
        float a = 0.f;
        #pragma unroll
        for (int j = 0; j < 64; j++) a += hs[h*64 + j] * w2[j*HID + k];
        mcomb[idx] = a;
    }
    if (idx < NH) {
        float a = 0.f;
        #pragma unroll
        for (int j = 0; j < 64; j++) a += hs[idx*64 + j] * b2[j];
        cbias[idx] = a;
    }
}

// ---------------- head scores + top-12 mask (float4 loads) ----------------
__global__ __launch_bounds__(256)
void head_scores(const float* __restrict__ t1, const float* __restrict__ mcomb,
                 const float* __restrict__ cbias, float* __restrict__ mask)
{
    const int warp = (blockIdx.x * blockDim.x + threadIdx.x) >> 5;
    const int lane = threadIdx.x & 31;
    if (warp >= MROWS) return;
    const float4* row4 = (const float4*)(t1 + (size_t)warp * HID);
    const float4* mc4  = (const float4*)mcomb;

    float acc[NH];
    #pragma unroll
    for (int h = 0; h < NH; h++) acc[h] = 0.f;
    #pragma unroll
    for (int it = 0; it < 4; it++) {
        const int k4 = it * 32 + lane;
        const float4 a = row4[k4];
        #pragma unroll
        for (int h = 0; h < NH; h++) {
            const float4 m = mc4[h * (HID/4) + k4];
            acc[h] += a.x*m.x + a.y*m.y + a.z*m.z + a.w*m.w;
        }
    }
    #pragma unroll
    for (int h = 0; h < NH; h++)
        #pragma unroll
        for (int off = 16; off > 0; off >>= 1)
            acc[h] += __shfl_xor_sync(0xffffffffu, acc[h], off);

    if (lane == 0) {
        float sc[NH], tmp[NH];
        #pragma unroll
        for (int h = 0; h < NH; h++) { sc[h] = acc[h] + cbias[h]; tmp[h] = sc[h]; }
        float thr = 0.f;
        for (int it = 0; it < NH - 4; it++) {
            int bi = 0; float bv = tmp[0];
            #pragma unroll
            for (int h = 1; h < NH; h++) if (tmp[h] > bv) { bv = tmp[h]; bi = h; }
            thr = bv; tmp[bi] = -INFINITY;
        }
        const int s = warp >> 1, b = warp & 1;
        #pragma unroll
        for (int h = 0; h < NH; h++)
            mask[((size_t)(b * NH + h)) * S_LEN + s] = (sc[h] >= thr) ? 1.f : 0.f;
    }
}

// ---------------------------------------------------------------------------
extern "C" void kernel_launch(void* const* d_in, const int* in_sizes, int n_in,
                              void* d_out, int out_size)
{
    const float* query   = (const float*)d_in[0];
    const float* q_w     = (const float*)d_in[1];
    const float* q_b     = (const float*)d_in[2];
    const float* k_w     = (const float*)d_in[3];
    const float* k_b     = (const float*)d_in[4];
    const float* v_w     = (const float*)d_in[5];
    const float* v_b     = (const float*)d_in[6];
    const float* out_w   = (const float*)d_in[7];
    const float* out_b   = (const float*)d_in[8];
    const float* inf1_w  = (const float*)d_in[9];
    const float* inf1_b  = (const float*)d_in[10];
    const float* inf2_w  = (const float*)d_in[11];
    const float* inf2_b  = (const float*)d_in[12];
    const float* head_sig= (const float*)d_in[13];
    float* out = (float*)d_out;

    float *pqkv, *pctx, *pt1, *pmc, *pcb, *pmask, *pqr, *pwqkv, *pwo;
    cudaGetSymbolAddress((void**)&pqkv, g_qkv);
    cudaGetSymbolAddress((void**)&pctx, g_ctx);
    cudaGetSymbolAddress((void**)&pt1,  g_t1);
    cudaGetSymbolAddress((void**)&pmc,  g_mcomb);
    cudaGetSymbolAddress((void**)&pcb,  g_cbias);
    cudaGetSymbolAddress((void**)&pmask,g_mask);
    cudaGetSymbolAddress((void**)&pqr,  g_qr);
    cudaGetSymbolAddress((void**)&pwqkv,g_wqkv);
    cudaGetSymbolAddress((void**)&pwo,  g_wo);

    const int GS  = 81920;   // k-permuted GEMM: 2 stages x 10240 words
    const int GS3 = 73728;   // 3x-relu: old stride-36 layout
    cudaFuncSetAttribute(mgemm_qkv, cudaFuncAttributeMaxDynamicSharedMemorySize, GS);
    cudaFuncSetAttribute(mgemm_out, cudaFuncAttributeMaxDynamicSharedMemorySize, GS);
    cudaFuncSetAttribute(mgemm_3x_relu, cudaFuncAttributeMaxDynamicSharedMemorySize, GS3);
    const int FS = 17920 * (int)sizeof(uint32_t);   // 71680 B
    cudaFuncSetAttribute(flash_tc, cudaFuncAttributeMaxDynamicSharedMemorySize, FS);

    // side stream + events (created per call; never destroyed so the captured
    // graph's references stay valid)
    cudaStream_t s2;
    cudaEvent_t eFork, eJoin, eF1, eO1;
    cudaStreamCreateWithFlags(&s2, cudaStreamNonBlocking);
    cudaEventCreateWithFlags(&eFork, cudaEventDisableTiming);
    cudaEventCreateWithFlags(&eJoin, cudaEventDisableTiming);
    cudaEventCreateWithFlags(&eF1,   cudaEventDisableTiming);
    cudaEventCreateWithFlags(&eO1,   cudaEventDisableTiming);

    cudaEventRecord(eFork, 0);
    cudaStreamWaitEvent(s2, eFork, 0);

    // --- side stream: combine_sig -> 3x MLP -> head_scores -----------------
    combine_sig<<<(NH*HID + 255)/256, 256, 0, s2>>>(head_sig, inf2_w, inf2_b,
                                                    pmc, pcb);
    {
        dim3 g(HID/128, MROWS/128);
        mgemm_3x_relu<<<g, 256, GS3, s2>>>(query, inf1_w, inf1_b, pt1, EMB);
    }
    head_scores<<<MROWS/8, 256, 0, s2>>>(pt1, pmc, pcb, pmask);
    cudaEventRecord(eJoin, s2);

    // --- main stream: round -> QKV ------------------------------------------
    {
        const int total = NQ4 + 4 * NW4;
        round_all<<<(total + 255)/256, 256>>>(query, q_w, k_w, v_w, out_w,
                                              pqr, pwqkv, pwo);
    }
    {
        dim3 g(EMB/128, MROWS/128, 3);
        mgemm_qkv<<<g, 256, GS>>>(pqr, pwqkv, q_b, k_b, v_b, pqkv, EMB);
    }

    cudaStreamWaitEvent(0, eJoin, 0);

    // --- flash split by s-half; out-proj overlaps second half ---------------
    {
        dim3 g(S_LEN/256, BATCH*NH);                 // 8 x 32
        flash_tc<<<g, 256, FS>>>(pqkv, pqkv + HSZ, pqkv + 2*HSZ, pmask, pctx, 0);
        cudaEventRecord(eF1, 0);
        flash_tc<<<g, 256, FS>>>(pqkv, pqkv + HSZ, pqkv + 2*HSZ, pmask, pctx,
                                 S_LEN/2);
    }
    // out1 on side stream: rows [0, 2048) = s-half 1, concurrent with flash2
    cudaStreamWaitEvent(s2, eF1, 0);
    {
        dim3 g(EMB/128, MROWS/256);                  // 8 x 16
        mgemm_out<<<g, 256, GS, s2>>>(pctx, pwo, out_b, out, EMB, 0);
    }
    cudaEventRecord(eO1, s2);
    // out2 on main after flash2
    {
        dim3 g(EMB/128, MROWS/256);
        mgemm_out<<<g, 256, GS>>>(pctx, pwo, out_b, out, EMB, MROWS/2);
    }
    cudaStreamWaitEvent(0, eO1, 0);
    (void)in_sizes; (void)n_in; (void)out_size;
}

// round 12
// speedup vs baseline: 1.4613x; 1.4613x over previous
#include <cuda_runtime.h>
#include <cuda_fp16.h>
#include <math.h>
#include <stdint.h>

#define S_LEN 2048
#define BATCH 2
#define EMB   1024
#define NH    16
#define HD    64
#define HID   512
#define MROWS (S_LEN*BATCH)   // 4096
#define HSZ   (BATCH*NH*S_LEN*HD)
#define LOG2E 1.4426950408889634f

// ---------------- scratch (static device globals; no allocation) ----------
__device__ __align__(16) __half g_qkv[3*HSZ];      // q|k fp16 (B,H,S,D); v fp16 (B,H,D,S)
__device__ __align__(16) __half g_ctx[MROWS*EMB];  // (S,B,E) fp16
__device__ float  g_t1 [MROWS*HID];
__device__ float  g_mcomb[NH*HID];
__device__ float  g_cbias[NH];
__device__ float  g_mask[BATCH*NH*S_LEN];
__device__ __align__(16) __half g_qh  [MROWS*EMB]; // fp16 query
__device__ __align__(16) __half g_wqkv[3*EMB*EMB]; // fp16 q_w|k_w|v_w
__device__ __align__(16) __half g_wo  [EMB*EMB];   // fp16 out_w

// =================== helpers ===============================================
__device__ __forceinline__ uint32_t f2tf(float x) {
    uint32_t r; asm("cvt.rna.tf32.f32 %0, %1;" : "=r"(r) : "f"(x)); return r;
}
__device__ __forceinline__ uint32_t smem_u32(const void* p) {
    uint32_t a;
    asm("{ .reg .u64 t; cvta.to.shared.u64 t, %1; cvt.u32.u64 %0, t; }"
        : "=r"(a) : "l"(p));
    return a;
}
__device__ __forceinline__ void cp16(uint32_t saddr, const void* g) {
    asm volatile("cp.async.cg.shared.global [%0], [%1], 16;"
                 :: "r"(saddr), "l"(g) : "memory");
}
__device__ __forceinline__ void mma_f16(float* d, const uint32_t* a, const uint32_t* b) {
    asm volatile(
        "mma.sync.aligned.m16n8k16.row.col.f32.f16.f16.f32 "
        "{%0,%1,%2,%3}, {%4,%5,%6,%7}, {%8,%9}, {%0,%1,%2,%3};"
        : "+f"(d[0]), "+f"(d[1]), "+f"(d[2]), "+f"(d[3])
        : "r"(a[0]), "r"(a[1]), "r"(a[2]), "r"(a[3]), "r"(b[0]), "r"(b[1]));
}
__device__ __forceinline__ void mma_tf32(float* d, const uint32_t* a, const uint32_t* b) {
    asm volatile(
        "mma.sync.aligned.m16n8k8.row.col.f32.tf32.tf32.f32 "
        "{%0,%1,%2,%3}, {%4,%5,%6,%7}, {%8,%9}, {%0,%1,%2,%3};"
        : "+f"(d[0]), "+f"(d[1]), "+f"(d[2]), "+f"(d[3])
        : "r"(a[0]), "r"(a[1]), "r"(a[2]), "r"(a[3]), "r"(b[0]), "r"(b[1]));
}
__device__ __forceinline__ uint32_t h2u(__half2 h) {
    return *(uint32_t*)&h;
}

// ---------------- fused fp16 conversion of query + 4 weight matrices ------
#define NQ4 (MROWS*EMB/4)      // 1048576
#define NW4 (EMB*EMB/4)        // 262144 = 1<<18
__global__ void round_all(const float* __restrict__ q,
                          const float* __restrict__ wq,
                          const float* __restrict__ wk,
                          const float* __restrict__ wv,
                          const float* __restrict__ wo,
                          __half* __restrict__ dq,
                          __half* __restrict__ dwqkv,
                          __half* __restrict__ dwo)
{
    const int i = blockIdx.x * blockDim.x + threadIdx.x;
    const float4* src; __half* dst; int off;
    if (i < NQ4) { src = (const float4*)q; dst = dq; off = i; }
    else {
        const int j = i - NQ4;
        const int z = j >> 18;
        off = j & (NW4 - 1);
        if      (z == 0) { src = (const float4*)wq; dst = dwqkv; }
        else if (z == 1) { src = (const float4*)wk; dst = dwqkv + 4*NW4; }
        else if (z == 2) { src = (const float4*)wv; dst = dwqkv + 8*NW4; }
        else             { src = (const float4*)wo; dst = dwo; }
    }
    float4 v = src[off];
    __half2 lo = __floats2half2_rn(v.x, v.y);
    __half2 hi = __floats2half2_rn(v.z, v.w);
    uint2 pk = { h2u(lo), h2u(hi) };
    *(uint2*)(dst + (size_t)off * 4) = pk;
}

// =================== cp.async pipelined fp16 GEMM core =====================
// A:(M,K) rm fp16, W:(N,K) rm fp16. K-chunks of 32 halves; row pad 40 halves.
// Stage: A 5120 halves @0, W 5120 @5120; stage stride 10240 halves (20480 B).
#define HGEMM_BODY(Ag, Wg)                                                     \
    float acc[4][4][4];                                                        \
    _Pragma("unroll")                                                          \
    for (int i = 0; i < 4; i++)                                                \
        _Pragma("unroll")                                                      \
        for (int j = 0; j < 4; j++)                                            \
            _Pragma("unroll")                                                  \
            for (int f = 0; f < 4; f++) acc[i][j][f] = 0.f;                    \
    const int NC = K >> 5;                                                     \
    const int r0 = tid >> 2;            /* 0..63 */                            \
    const int sg = tid & 3;             /* 4 segs of 16B per 32-half row */    \
    {                                                                          \
        const uint32_t ab = sbase, wb = sbase + 5120u * 2u;                    \
        _Pragma("unroll")                                                      \
        for (int i = 0; i < 2; i++) {                                          \
            const int row = r0 + i * 64;                                       \
            const uint32_t off = (uint32_t)(row * 40 + sg * 8) * 2u;           \
            cp16(ab + off, Ag + (size_t)row * K + sg * 8);                     \
            cp16(wb + off, Wg + (size_t)row * K + sg * 8);                     \
        }                                                                      \
        asm volatile("cp.async.commit_group;" ::: "memory");                   \
    }                                                                          \
    for (int c = 0; c < NC; c++) {                                             \
        if (c + 1 < NC) {                                                      \
            const uint32_t st = (uint32_t)((c + 1) & 1) * 10240u * 2u;         \
            const uint32_t ab = sbase + st, wb = sbase + st + 5120u * 2u;      \
            const int kn = (c + 1) << 5;                                       \
            _Pragma("unroll")                                                  \
            for (int i = 0; i < 2; i++) {                                      \
                const int row = r0 + i * 64;                                   \
                const uint32_t off = (uint32_t)(row * 40 + sg * 8) * 2u;       \
                cp16(ab + off, Ag + (size_t)row * K + kn + sg * 8);            \
                cp16(wb + off, Wg + (size_t)row * K + kn + sg * 8);            \
            }                                                                  \
            asm volatile("cp.async.commit_group;" ::: "memory");               \
            asm volatile("cp.async.wait_group 1;" ::: "memory");               \
        } else {                                                               \
            asm volatile("cp.async.wait_group 0;" ::: "memory");               \
        }                                                                      \
        __syncthreads();                                                       \
        const __half* As = swh + (c & 1) * 10240;                              \
        const __half* Ws = As + 5120;                                          \
        _Pragma("unroll")                                                      \
        for (int ks = 0; ks < 2; ks++) {                                       \
            const int k0 = ks * 16;                                            \
            uint32_t af[4][4];                                                 \
            _Pragma("unroll")                                                  \
            for (int mt = 0; mt < 4; mt++) {                                   \
                const int r = wm * 64 + mt * 16 + gid;                         \
                af[mt][0] = *(const uint32_t*)&As[ r      * 40 + k0 + 2*tig    ];\
                af[mt][1] = *(const uint32_t*)&As[(r + 8) * 40 + k0 + 2*tig    ];\
                af[mt][2] = *(const uint32_t*)&As[ r      * 40 + k0 + 2*tig + 8];\
                af[mt][3] = *(const uint32_t*)&As[(r + 8) * 40 + k0 + 2*tig + 8];\
            }                                                                  \
            uint32_t bf[4][2];                                                 \
            _Pragma("unroll")                                                  \
            for (int nt = 0; nt < 4; nt++) {                                   \
                const int n = wn * 32 + nt * 8 + gid;                          \
                bf[nt][0] = *(const uint32_t*)&Ws[n * 40 + k0 + 2*tig    ];    \
                bf[nt][1] = *(const uint32_t*)&Ws[n * 40 + k0 + 2*tig + 8];    \
            }                                                                  \
            _Pragma("unroll")                                                  \
            for (int mt = 0; mt < 4; mt++)                                     \
                _Pragma("unroll")                                              \
                for (int nt = 0; nt < 4; nt++)                                 \
                    mma_f16(acc[mt][nt], af[mt], bf[nt]);                      \
        }                                                                      \
        __syncthreads();                                                       \
    }

// ---- fused QKV projection: q/k -> (B,H,S,D) fp16; v -> (B,H,D,S) fp16 -----
__global__ __launch_bounds__(256, 2)
void hgemm_qkv(const __half* __restrict__ A, const __half* __restrict__ Wall,
               const float* __restrict__ bq, const float* __restrict__ bk,
               const float* __restrict__ bv, __half* __restrict__ Call, int K)
{
    extern __shared__ __align__(16) char smemraw[];
    __half* swh = (__half*)smemraw;
    const uint32_t sbase = smem_u32(swh);
    const int tid  = threadIdx.x;
    const int wid  = tid >> 5;
    const int lane = tid & 31;
    const int gid  = lane >> 2;
    const int tig  = lane & 3;
    const int wm   = wid >> 2;
    const int wn   = wid & 3;
    const int z    = blockIdx.z;

    const __half* Ag = A + (size_t)blockIdx.y * 128 * K;
    const __half* Wg = Wall + (size_t)z * EMB * EMB + (size_t)blockIdx.x * 128 * K;
    const float* bias = (z == 0) ? bq : (z == 1) ? bk : bv;
    __half* C = Call + (size_t)z * HSZ;
    const float scale = (z == 0) ? 0.125f * LOG2E : 1.f;

    HGEMM_BODY(Ag, Wg)

    #pragma unroll
    for (int mt = 0; mt < 4; mt++) {
        #pragma unroll
        for (int nt = 0; nt < 4; nt++) {
            const int n = blockIdx.x * 128 + wn * 32 + nt * 8 + tig * 2;
            const float b0 = bias[n], b1 = bias[n + 1];
            #pragma unroll
            for (int half_ = 0; half_ < 2; half_++) {
                const int m = blockIdx.y * 128 + wm * 64 + mt * 16 + gid + half_ * 8;
                const float vx = (acc[mt][nt][half_ * 2 + 0] + b0) * scale;
                const float vy = (acc[mt][nt][half_ * 2 + 1] + b1) * scale;
                const int s = m >> 1, b = m & 1;
                const int h = n >> 6, d = n & 63;
                if (z < 2) {
                    __half2 hv = __floats2half2_rn(vx, vy);
                    *(uint32_t*)(C + (((size_t)(b * NH + h)) * S_LEN + s) * HD + d) = h2u(hv);
                } else {
                    // V transposed: (B,H,D,S)
                    C[(((size_t)(b * NH + h)) * HD + d    ) * S_LEN + s] = __float2half_rn(vx);
                    C[(((size_t)(b * NH + h)) * HD + d + 1) * S_LEN + s] = __float2half_rn(vy);
                }
            }
        }
    }
}

// ---- output projection: ctx fp16 @ wo fp16 -> fp32 out --------------------
__global__ __launch_bounds__(256, 2)
void hgemm_out(const __half* __restrict__ A, const __half* __restrict__ W,
               const float* __restrict__ bias, float* __restrict__ C, int K)
{
    extern __shared__ __align__(16) char smemraw[];
    __half* swh = (__half*)smemraw;
    const uint32_t sbase = smem_u32(swh);
    const int tid  = threadIdx.x;
    const int wid  = tid >> 5;
    const int lane = tid & 31;
    const int gid  = lane >> 2;
    const int tig  = lane & 3;
    const int wm   = wid >> 2;
    const int wn   = wid & 3;

    const __half* Ag = A + (size_t)blockIdx.y * 128 * K;
    const __half* Wg = W + (size_t)blockIdx.x * 128 * K;

    HGEMM_BODY(Ag, Wg)

    #pragma unroll
    for (int mt = 0; mt < 4; mt++) {
        #pragma unroll
        for (int nt = 0; nt < 4; nt++) {
            const int n = blockIdx.x * 128 + wn * 32 + nt * 8 + tig * 2;
            const float b0 = bias[n], b1 = bias[n + 1];
            #pragma unroll
            for (int half_ = 0; half_ < 2; half_++) {
                const int m = blockIdx.y * 128 + wm * 64 + mt * 16 + gid + half_ * 8;
                float2 v;
                v.x = acc[mt][nt][half_ * 2 + 0] + b0;
                v.y = acc[mt][nt][half_ * 2 + 1] + b1;
                *(float2*)(C + (size_t)m * (gridDim.x * 128) + n) = v;
            }
        }
    }
}

// =================== split-tf32 (3xMMA) GEMM + ReLU for the mask MLP =======
// (unchanged; exact-ish fp32; hidden on the side stream)
__global__ __launch_bounds__(256)
void mgemm_3x_relu(const float* __restrict__ A, const float* __restrict__ W,
                   const float* __restrict__ bias, float* __restrict__ C, int K)
{
    extern __shared__ __align__(16) char smemraw[];
    uint32_t* sw = (uint32_t*)smemraw;
    const uint32_t sbase = smem_u32(sw);
    const float* swf = (const float*)sw;
    const int tid  = threadIdx.x;
    const int wid  = tid >> 5;
    const int lane = tid & 31;
    const int gid  = lane >> 2;
    const int tig  = lane & 3;
    const int wm   = wid >> 2;
    const int wn   = wid & 3;

    const float* Ag = A + (size_t)blockIdx.y * 128 * K;
    const float* Wg = W + (size_t)blockIdx.x * 128 * K;

    float acc[4][4][4];
    #pragma unroll
    for (int i = 0; i < 4; i++)
        #pragma unroll
        for (int j = 0; j < 4; j++)
            #pragma unroll
            for (int f = 0; f < 4; f++) acc[i][j][f] = 0.f;

    const int NC = K >> 5;
    const int r0 = tid >> 3;
    const int sg = tid & 7;

    {
        const uint32_t ab = sbase, wb = sbase + 4608u * 4u;
        #pragma unroll
        for (int i = 0; i < 4; i++) {
            const int row = r0 + i * 32;
            const uint32_t off = (uint32_t)(row * 36 + sg * 4) * 4u;
            cp16(ab + off, Ag + (size_t)row * K + sg * 4);
            cp16(wb + off, Wg + (size_t)row * K + sg * 4);
        }
        asm volatile("cp.async.commit_group;" ::: "memory");
    }

    for (int c = 0; c < NC; c++) {
        if (c + 1 < NC) {
            const uint32_t st = (uint32_t)((c + 1) & 1) * 9216u * 4u;
            const uint32_t ab = sbase + st, wb = sbase + st + 4608u * 4u;
            const int kn = (c + 1) << 5;
            #pragma unroll
            for (int i = 0; i < 4; i++) {
                const int row = r0 + i * 32;
                const uint32_t off = (uint32_t)(row * 36 + sg * 4) * 4u;
                cp16(ab + off, Ag + (size_t)row * K + kn + sg * 4);
                cp16(wb + off, Wg + (size_t)row * K + kn + sg * 4);
            }
            asm volatile("cp.async.commit_group;" ::: "memory");
            asm volatile("cp.async.wait_group 1;" ::: "memory");
        } else {
            asm volatile("cp.async.wait_group 0;" ::: "memory");
        }
        __syncthreads();

        const float* As = swf + (c & 1) * 9216;
        const float* Ws = As + 4608;
        #pragma unroll
        for (int ks = 0; ks < 4; ks++) {
            const int k0 = ks * 8;
            uint32_t ah[4][4], al[4][4];
            #pragma unroll
            for (int mt = 0; mt < 4; mt++) {
                const int r = wm * 64 + mt * 16 + gid;
                float a0 = As[ r      * 36 + k0 + tig    ];
                float a1 = As[(r + 8) * 36 + k0 + tig    ];
                float a2 = As[ r      * 36 + k0 + tig + 4];
                float a3 = As[(r + 8) * 36 + k0 + tig + 4];
                ah[mt][0] = f2tf(a0); al[mt][0] = f2tf(a0 - __uint_as_float(ah[mt][0]));
                ah[mt][1] = f2tf(a1); al[mt][1] = f2tf(a1 - __uint_as_float(ah[mt][1]));
                ah[mt][2] = f2tf(a2); al[mt][2] = f2tf(a2 - __uint_as_float(ah[mt][2]));
                ah[mt][3] = f2tf(a3); al[mt][3] = f2tf(a3 - __uint_as_float(ah[mt][3]));
            }
            uint32_t bh_[4][2], bl_[4][2];
            #pragma unroll
            for (int nt = 0; nt < 4; nt++) {
                const int n = wn * 32 + nt * 8 + gid;
                float b0 = Ws[n * 36 + k0 + tig    ];
                float b1 = Ws[n * 36 + k0 + tig + 4];
                bh_[nt][0] = f2tf(b0); bl_[nt][0] = f2tf(b0 - __uint_as_float(bh_[nt][0]));
                bh_[nt][1] = f2tf(b1); bl_[nt][1] = f2tf(b1 - __uint_as_float(bh_[nt][1]));
            }
            #pragma unroll
            for (int mt = 0; mt < 4; mt++)
                #pragma unroll
                for (int nt = 0; nt < 4; nt++) {
                    mma_tf32(acc[mt][nt], al[mt], bh_[nt]);
                    mma_tf32(acc[mt][nt], ah[mt], bl_[nt]);
                    mma_tf32(acc[mt][nt], ah[mt], bh_[nt]);
                }
        }
        __syncthreads();
    }

    #pragma unroll
    for (int mt = 0; mt < 4; mt++) {
        #pragma unroll
        for (int nt = 0; nt < 4; nt++) {
            const int n = blockIdx.x * 128 + wn * 32 + nt * 8 + tig * 2;
            const float b0 = bias[n], b1 = bias[n + 1];
            #pragma unroll
            for (int half_ = 0; half_ < 2; half_++) {
                const int m = blockIdx.y * 128 + wm * 64 + mt * 16 + gid + half_ * 8;
                float2 v;
                v.x = fmaxf(acc[mt][nt][half_ * 2 + 0] + b0, 0.f);
                v.y = fmaxf(acc[mt][nt][half_ * 2 + 1] + b1, 0.f);
                *(float2*)(C + (size_t)m * (gridDim.x * 128) + n) = v;
            }
        }
    }
}

// =================== fp16 tensor-core flash attention ======================
// Q,K fp16 (B,H,S,D); V fp16 transposed (B,H,D,S). exp2 softmax (Q pre-scaled).
// smem halves: stage0 K @0 (64x72), stage0 Vt @4608, stage1 @9216/@13824.
// Total 18432 halves = 36864 B. Q staged transiently in stage0 region.
__global__ __launch_bounds__(256, 2)
void flash_h(const __half* __restrict__ Q, const __half* __restrict__ Kg,
             const __half* __restrict__ Vg, const float* __restrict__ gate,
             __half* __restrict__ ctx)
{
    extern __shared__ __align__(16) char smemraw[];
    __half* swh = (__half*)smemraw;
    const uint32_t sbase = smem_u32(swh);
    const int tid  = threadIdx.x;
    const int wid  = tid >> 5;
    const int lane = tid & 31;
    const int gid  = lane >> 2;
    const int tig  = lane & 3;
    const int bh   = blockIdx.y;
    const int b    = bh >> 4, h = bh & 15;
    const int q0   = blockIdx.x * 128;

    const __half* Qt = Q  + ((size_t)bh * S_LEN + q0) * HD;
    const __half* Kb = Kg + (size_t)bh * S_LEN * HD;
    const __half* Vb = Vg + (size_t)bh * HD * S_LEN;   // transposed

    // ---- stage Q (pad 72 halves) then extract fp16 fragments ---------------
    #pragma unroll
    for (int i = 0; i < 4; i++) {
        const int fi = tid + i * 256;            // 0..1023 segs of 8 halves
        const int r = fi >> 3, seg = fi & 7;
        uint4 v = *(const uint4*)(Qt + r * 64 + seg * 8);
        *(uint4*)(swh + r * 72 + seg * 8) = v;
    }
    __syncthreads();
    uint32_t qa[4][4];
    {
        const int r0q = wid * 16 + gid;
        #pragma unroll
        for (int ks = 0; ks < 4; ks++) {
            const int k0 = ks * 16;
            qa[ks][0] = *(const uint32_t*)&swh[ r0q      * 72 + k0 + 2*tig    ];
            qa[ks][1] = *(const uint32_t*)&swh[(r0q + 8) * 72 + k0 + 2*tig    ];
            qa[ks][2] = *(const uint32_t*)&swh[ r0q      * 72 + k0 + 2*tig + 8];
            qa[ks][3] = *(const uint32_t*)&swh[(r0q + 8) * 72 + k0 + 2*tig + 8];
        }
    }
    __syncthreads();

    // ---- issue first two K/V tiles -----------------------------------------
    #pragma unroll 1
    for (int t = 0; t < 2; t++) {
        const uint32_t kb = sbase + (uint32_t)t * 9216u * 2u;
        const uint32_t vb = kb + 4608u * 2u;
        const __half* Ksrc = Kb + (size_t)t * 64 * 64;
        const __half* Vsrc = Vb + (size_t)t * 64;       // keys t*64.. along S
        #pragma unroll
        for (int i = 0; i < 4; i++) {
            const int fi = tid + i * 256;    // 0..1023; first 512 K, next 512 V
            const int half_sel = fi >> 9;
            const int j = fi & 511;
            const int r = j >> 3, seg = j & 7;
            if (half_sel == 0)
                cp16(kb + (uint32_t)(r * 72 + seg * 8) * 2u, Ksrc + r * 64 + seg * 8);
            else
                cp16(vb + (uint32_t)(r * 72 + seg * 8) * 2u, Vsrc + (size_t)r * S_LEN + seg * 8);
        }
        asm volatile("cp.async.commit_group;" ::: "memory");
    }

    float miA = -INFINITY, miB = -INFINITY, liA = 0.f, liB = 0.f;
    float oa[8][4];
    #pragma unroll
    for (int nt = 0; nt < 8; nt++)
        #pragma unroll
        for (int f = 0; f < 4; f++) oa[nt][f] = 0.f;

    const int NT = S_LEN / 64;
    for (int t = 0; t < NT; t++) {
        if (t < NT - 2) asm volatile("cp.async.wait_group 1;" ::: "memory");
        else            asm volatile("cp.async.wait_group 0;" ::: "memory");
        __syncthreads();
        const __half* Ks = swh + (t & 1) * 9216;
        const __half* Vs = Ks + 4608;

        // ---- S = Q K^T (4 k16 steps x 8 key tiles) -------------------------
        float sa[8][4];
        #pragma unroll
        for (int nt = 0; nt < 8; nt++)
            #pragma unroll
            for (int f = 0; f < 4; f++) sa[nt][f] = 0.f;
        #pragma unroll
        for (int ks = 0; ks < 4; ks++) {
            const int k0 = ks * 16;
            #pragma unroll
            for (int nt = 0; nt < 8; nt++) {
                uint32_t bf[2];
                bf[0] = *(const uint32_t*)&Ks[(nt * 8 + gid) * 72 + k0 + 2*tig    ];
                bf[1] = *(const uint32_t*)&Ks[(nt * 8 + gid) * 72 + k0 + 2*tig + 8];
                mma_f16(sa[nt], qa[ks], bf);
            }
        }

        // ---- online softmax (exp2 domain) ----------------------------------
        float rmA = -INFINITY, rmB = -INFINITY;
        #pragma unroll
        for (int nt = 0; nt < 8; nt++) {
            rmA = fmaxf(rmA, fmaxf(sa[nt][0], sa[nt][1]));
            rmB = fmaxf(rmB, fmaxf(sa[nt][2], sa[nt][3]));
        }
        rmA = fmaxf(rmA, __shfl_xor_sync(0xffffffffu, rmA, 1));
        rmA = fmaxf(rmA, __shfl_xor_sync(0xffffffffu, rmA, 2));
        rmB = fmaxf(rmB, __shfl_xor_sync(0xffffffffu, rmB, 1));
        rmB = fmaxf(rmB, __shfl_xor_sync(0xffffffffu, rmB, 2));

        const float mAn = fmaxf(miA, rmA);
        const float mBn = fmaxf(miB, rmB);
        const float aA  = exp2f(miA - mAn);
        const float aB  = exp2f(miB - mBn);
        miA = mAn; miB = mBn;

        float rsA = 0.f, rsB = 0.f;
        #pragma unroll
        for (int nt = 0; nt < 8; nt++) {
            sa[nt][0] = exp2f(sa[nt][0] - mAn);
            sa[nt][1] = exp2f(sa[nt][1] - mAn);
            sa[nt][2] = exp2f(sa[nt][2] - mBn);
            sa[nt][3] = exp2f(sa[nt][3] - mBn);
            rsA += sa[nt][0] + sa[nt][1];
            rsB += sa[nt][2] + sa[nt][3];
        }
        rsA += __shfl_xor_sync(0xffffffffu, rsA, 1);
        rsA += __shfl_xor_sync(0xffffffffu, rsA, 2);
        rsB += __shfl_xor_sync(0xffffffffu, rsB, 1);
        rsB += __shfl_xor_sync(0xffffffffu, rsB, 2);
        liA = liA * aA + rsA;
        liB = liB * aB + rsB;
        #pragma unroll
        for (int nt = 0; nt < 8; nt++) {
            oa[nt][0] *= aA; oa[nt][1] *= aA;
            oa[nt][2] *= aB; oa[nt][3] *= aB;
        }

        // ---- O += P V (P packed to fp16 A-frags; V from transposed tile) ---
        #pragma unroll
        for (int kk = 0; kk < 4; kk++) {
            uint32_t af[4];
            af[0] = h2u(__floats2half2_rn(sa[2*kk  ][0], sa[2*kk  ][1]));
            af[1] = h2u(__floats2half2_rn(sa[2*kk  ][2], sa[2*kk  ][3]));
            af[2] = h2u(__floats2half2_rn(sa[2*kk+1][0], sa[2*kk+1][1]));
            af[3] = h2u(__floats2half2_rn(sa[2*kk+1][2], sa[2*kk+1][3]));
            const int k0 = kk * 16;
            #pragma unroll
            for (int nt = 0; nt < 8; nt++) {
                uint32_t bf[2];
                bf[0] = *(const uint32_t*)&Vs[(nt * 8 + gid) * 72 + k0 + 2*tig    ];
                bf[1] = *(const uint32_t*)&Vs[(nt * 8 + gid) * 72 + k0 + 2*tig + 8];
                mma_f16(oa[nt], af, bf);
            }
        }
        __syncthreads();

        // ---- prefetch tile t+2 ---------------------------------------------
        if (t + 2 < NT) {
            const uint32_t kb = sbase + (uint32_t)(t & 1) * 9216u * 2u;
            const uint32_t vb = kb + 4608u * 2u;
            const __half* Ksrc = Kb + (size_t)(t + 2) * 64 * 64;
            const __half* Vsrc = Vb + (size_t)(t + 2) * 64;
            #pragma unroll
            for (int i = 0; i < 4; i++) {
                const int fi = tid + i * 256;
                const int half_sel = fi >> 9;
                const int j = fi & 511;
                const int r = j >> 3, seg = j & 7;
                if (half_sel == 0)
                    cp16(kb + (uint32_t)(r * 72 + seg * 8) * 2u, Ksrc + r * 64 + seg * 8);
                else
                    cp16(vb + (uint32_t)(r * 72 + seg * 8) * 2u, Vsrc + (size_t)r * S_LEN + seg * 8);
            }
            asm volatile("cp.async.commit_group;" ::: "memory");
        }
    }

    // ---- epilogue: normalize, gate, write ctx fp16 (S,B,E) -----------------
    const int sA = q0 + wid * 16 + gid;
    const int sB = sA + 8;
    const float gA = gate[(size_t)bh * S_LEN + sA];
    const float gB = gate[(size_t)bh * S_LEN + sB];
    const float invA = gA / liA;
    const float invB = gB / liB;
    #pragma unroll
    for (int nt = 0; nt < 8; nt++) {
        const int col = h * 64 + nt * 8 + tig * 2;
        __half2 va = __floats2half2_rn(oa[nt][0] * invA, oa[nt][1] * invA);
        __half2 vb = __floats2half2_rn(oa[nt][2] * invB, oa[nt][3] * invB);
        *(uint32_t*)(ctx + ((size_t)sA * BATCH + b) * EMB + col) = h2u(va);
        *(uint32_t*)(ctx + ((size_t)sB * BATCH + b) * EMB + col) = h2u(vb);
    }
}

// ---------------- fold head_sig into inf2 ---------------------------------
__global__ void combine_sig(const float* __restrict__ hs,
                            const float* __restrict__ w2,
                            const float* __restrict__ b2,
                            float* __restrict__ mcomb,
                            float* __restrict__ cbias)
{
    const int idx = blockIdx.x * blockDim.x + threadIdx.x;
    if (idx < NH * HID) {
        const int h = idx / HID, k = idx % HID;
        float a = 0.f;
        #pragma unroll
        for (int j = 0; j < 64; j++) a += hs[h*64 + j] * w2[j*HID + k];
        mcomb[idx] = a;
    }
    if (idx < NH) {
        float a = 0.f;
        #pragma unroll
        for (int j = 0; j < 64; j++) a += hs[idx*64 + j] * b2[j];
        cbias[idx] = a;
    }
}

// ---------------- head scores + top-12 mask (float4 loads) ----------------
__global__ __launch_bounds__(256)
void head_scores(const float* __restrict__ t1, const float* __restrict__ mcomb,
                 const float* __restrict__ cbias, float* __restrict__ mask)
{
    const int warp = (blockIdx.x * blockDim.x + threadIdx.x) >> 5;
    const int lane = threadIdx.x & 31;
    if (warp >= MROWS) return;
    const float4* row4 = (const float4*)(t1 + (size_t)warp * HID);
    const float4* mc4  = (const float4*)mcomb;

    float acc[NH];
    #pragma unroll
    for (int h = 0; h < NH; h++) acc[h] = 0.f;
    #pragma unroll
    for (int it = 0; it < 4; it++) {
        const int k4 = it * 32 + lane;
        const float4 a = row4[k4];
        #pragma unroll
        for (int h = 0; h < NH; h++) {
            const float4 m = mc4[h * (HID/4) + k4];
            acc[h] += a.x*m.x + a.y*m.y + a.z*m.z + a.w*m.w;
        }
    }
    #pragma unroll
    for (int h = 0; h < NH; h++)
        #pragma unroll
        for (int off = 16; off > 0; off >>= 1)
            acc[h] += __shfl_xor_sync(0xffffffffu, acc[h], off);

    if (lane == 0) {
        float sc[NH], tmp[NH];
        #pragma unroll
        for (int h = 0; h < NH; h++) { sc[h] = acc[h] + cbias[h]; tmp[h] = sc[h]; }
        float thr = 0.f;
        for (int it = 0; it < NH - 4; it++) {
            int bi = 0; float bv = tmp[0];
            #pragma unroll
            for (int h = 1; h < NH; h++) if (tmp[h] > bv) { bv = tmp[h]; bi = h; }
            thr = bv; tmp[bi] = -INFINITY;
        }
        const int s = warp >> 1, b = warp & 1;
        #pragma unroll
        for (int h = 0; h < NH; h++)
            mask[((size_t)(b * NH + h)) * S_LEN + s] = (sc[h] >= thr) ? 1.f : 0.f;
    }
}

// ---------------------------------------------------------------------------
extern "C" void kernel_launch(void* const* d_in, const int* in_sizes, int n_in,
                              void* d_out, int out_size)
{
    const float* query   = (const float*)d_in[0];
    const float* q_w     = (const float*)d_in[1];
    const float* q_b     = (const float*)d_in[2];
    const float* k_w     = (const float*)d_in[3];
    const float* k_b     = (const float*)d_in[4];
    const float* v_w     = (const float*)d_in[5];
    const float* v_b     = (const float*)d_in[6];
    const float* out_w   = (const float*)d_in[7];
    const float* out_b   = (const float*)d_in[8];
    const float* inf1_w  = (const float*)d_in[9];
    const float* inf1_b  = (const float*)d_in[10];
    const float* inf2_w  = (const float*)d_in[11];
    const float* inf2_b  = (const float*)d_in[12];
    const float* head_sig= (const float*)d_in[13];
    float* out = (float*)d_out;

    __half *pqkv, *pctx, *pqh, *pwqkv, *pwo;
    float *pt1, *pmc, *pcb, *pmask;
    cudaGetSymbolAddress((void**)&pqkv, g_qkv);
    cudaGetSymbolAddress((void**)&pctx, g_ctx);
    cudaGetSymbolAddress((void**)&pt1,  g_t1);
    cudaGetSymbolAddress((void**)&pmc,  g_mcomb);
    cudaGetSymbolAddress((void**)&pcb,  g_cbias);
    cudaGetSymbolAddress((void**)&pmask,g_mask);
    cudaGetSymbolAddress((void**)&pqh,  g_qh);
    cudaGetSymbolAddress((void**)&pwqkv,g_wqkv);
    cudaGetSymbolAddress((void**)&pwo,  g_wo);

    const int HGS = 40960;   // fp16 GEMM: 2 stages x 10240 halves
    const int GS3 = 73728;   // 3x-relu fp32 layout
    const int FS  = 36864;   // flash fp16: 2 x (4608 + 4608) halves
    cudaFuncSetAttribute(hgemm_qkv, cudaFuncAttributeMaxDynamicSharedMemorySize, HGS);
    cudaFuncSetAttribute(hgemm_out, cudaFuncAttributeMaxDynamicSharedMemorySize, HGS);
    cudaFuncSetAttribute(mgemm_3x_relu, cudaFuncAttributeMaxDynamicSharedMemorySize, GS3);
    cudaFuncSetAttribute(flash_h, cudaFuncAttributeMaxDynamicSharedMemorySize, FS);

    // side stream + fork/join events (created per call; never destroyed so
    // the captured graph's references stay valid)
    cudaStream_t s2;
    cudaEvent_t eFork, eJoin;
    cudaStreamCreateWithFlags(&s2, cudaStreamNonBlocking);
    cudaEventCreateWithFlags(&eFork, cudaEventDisableTiming);
    cudaEventCreateWithFlags(&eJoin, cudaEventDisableTiming);

    cudaEventRecord(eFork, 0);
    cudaStreamWaitEvent(s2, eFork, 0);

    // --- side stream: combine_sig -> 3x MLP -> head_scores -----------------
    combine_sig<<<(NH*HID + 255)/256, 256, 0, s2>>>(head_sig, inf2_w, inf2_b,
                                                    pmc, pcb);
    {
        dim3 g(HID/128, MROWS/128);
        mgemm_3x_relu<<<g, 256, GS3, s2>>>(query, inf1_w, inf1_b, pt1, EMB);
    }
    head_scores<<<MROWS/8, 256, 0, s2>>>(pt1, pmc, pcb, pmask);
    cudaEventRecord(eJoin, s2);

    // --- main stream: fp16 convert -> QKV -----------------------------------
    {
        const int total = NQ4 + 4 * NW4;
        round_all<<<(total + 255)/256, 256>>>(query, q_w, k_w, v_w, out_w,
                                              pqh, pwqkv, pwo);
    }
    {
        dim3 g(EMB/128, MROWS/128, 3);
        hgemm_qkv<<<g, 256, HGS>>>(pqh, pwqkv, q_b, k_b, v_b, pqkv, EMB);
    }

    cudaStreamWaitEvent(0, eJoin, 0);

    // --- flash attention (fp16) -> ctx fp16 ---------------------------------
    {
        dim3 g(S_LEN/128, BATCH*NH);
        flash_h<<<g, 256, FS>>>(pqkv, pqkv + HSZ, pqkv + 2*HSZ, pmask, pctx);
    }
    // --- output projection ---------------------------------------------------
    {
        dim3 g(EMB/128, MROWS/128);
        hgemm_out<<<g, 256, HGS>>>(pctx, pwo, out_b, out, EMB);
    }
    (void)in_sizes; (void)n_in; (void)out_size;
}

// round 13
// speedup vs baseline: 1.5631x; 1.0697x over previous
#include <cuda_runtime.h>
#include <cuda_fp16.h>
#include <math.h>
#include <stdint.h>

#define S_LEN 2048
#define BATCH 2
#define EMB   1024
#define NH    16
#define HD    64
#define HID   512
#define MROWS (S_LEN*BATCH)   // 4096
#define HSZ   (BATCH*NH*S_LEN*HD)
#define LOG2E 1.4426950408889634f

// ---------------- scratch (static device globals; no allocation) ----------
__device__ __align__(16) __half g_qkv[3*HSZ];      // q|k fp16 (B,H,S,D); v fp16 (B,H,D,S)
__device__ __align__(16) __half g_ctx[MROWS*EMB];  // (S,B,E) fp16
__device__ float  g_t1 [MROWS*HID];
__device__ float  g_mcomb[NH*HID];
__device__ float  g_cbias[NH];
__device__ float  g_mask[BATCH*NH*S_LEN];
__device__ __align__(16) __half g_qh  [MROWS*EMB]; // fp16 query
__device__ __align__(16) __half g_wqkv[3*EMB*EMB]; // fp16 q_w|k_w|v_w
__device__ __align__(16) __half g_wo  [EMB*EMB];   // fp16 out_w

// =================== helpers ===============================================
__device__ __forceinline__ uint32_t f2tf(float x) {
    uint32_t r; asm("cvt.rna.tf32.f32 %0, %1;" : "=r"(r) : "f"(x)); return r;
}
__device__ __forceinline__ uint32_t smem_u32(const void* p) {
    uint32_t a;
    asm("{ .reg .u64 t; cvta.to.shared.u64 t, %1; cvt.u32.u64 %0, t; }"
        : "=r"(a) : "l"(p));
    return a;
}
__device__ __forceinline__ void cp16(uint32_t saddr, const void* g) {
    asm volatile("cp.async.cg.shared.global [%0], [%1], 16;"
                 :: "r"(saddr), "l"(g) : "memory");
}
__device__ __forceinline__ void mma_f16(float* d, const uint32_t* a, const uint32_t* b) {
    asm volatile(
        "mma.sync.aligned.m16n8k16.row.col.f32.f16.f16.f32 "
        "{%0,%1,%2,%3}, {%4,%5,%6,%7}, {%8,%9}, {%0,%1,%2,%3};"
        : "+f"(d[0]), "+f"(d[1]), "+f"(d[2]), "+f"(d[3])
        : "r"(a[0]), "r"(a[1]), "r"(a[2]), "r"(a[3]), "r"(b[0]), "r"(b[1]));
}
__device__ __forceinline__ void mma_tf32(float* d, const uint32_t* a, const uint32_t* b) {
    asm volatile(
        "mma.sync.aligned.m16n8k8.row.col.f32.tf32.tf32.f32 "
        "{%0,%1,%2,%3}, {%4,%5,%6,%7}, {%8,%9}, {%0,%1,%2,%3};"
        : "+f"(d[0]), "+f"(d[1]), "+f"(d[2]), "+f"(d[3])
        : "r"(a[0]), "r"(a[1]), "r"(a[2]), "r"(a[3]), "r"(b[0]), "r"(b[1]));
}
__device__ __forceinline__ uint32_t h2u(__half2 h) {
    return *(uint32_t*)&h;
}

// ---------------- fused fp16 conversion of query + 4 weight matrices ------
#define NQ4 (MROWS*EMB/4)      // 1048576
#define NW4 (EMB*EMB/4)        // 262144 = 1<<18
__global__ void round_all(const float* __restrict__ q,
                          const float* __restrict__ wq,
                          const float* __restrict__ wk,
                          const float* __restrict__ wv,
                          const float* __restrict__ wo,
                          __half* __restrict__ dq,
                          __half* __restrict__ dwqkv,
                          __half* __restrict__ dwo)
{
    const int i = blockIdx.x * blockDim.x + threadIdx.x;
    const float4* src; __half* dst; int off;
    if (i < NQ4) { src = (const float4*)q; dst = dq; off = i; }
    else {
        const int j = i - NQ4;
        const int z = j >> 18;
        off = j & (NW4 - 1);
        if      (z == 0) { src = (const float4*)wq; dst = dwqkv; }
        else if (z == 1) { src = (const float4*)wk; dst = dwqkv + 4*NW4; }
        else if (z == 2) { src = (const float4*)wv; dst = dwqkv + 8*NW4; }
        else             { src = (const float4*)wo; dst = dwo; }
    }
    float4 v = src[off];
    __half2 lo = __floats2half2_rn(v.x, v.y);
    __half2 hi = __floats2half2_rn(v.z, v.w);
    uint2 pk = { h2u(lo), h2u(hi) };
    *(uint2*)(dst + (size_t)off * 4) = pk;
}

// =================== cp.async pipelined fp16 GEMM core =====================
// K-chunks of 64 halves; row pad 72 halves. Stage: A 9216 halves @0, W @9216;
// stage stride 18432 halves (36864 B). 2 stages = 73728 B.
#define HGEMM_BODY(Ag, Wg)                                                     \
    float acc[4][4][4];                                                        \
    _Pragma("unroll")                                                          \
    for (int i = 0; i < 4; i++)                                                \
        _Pragma("unroll")                                                      \
        for (int j = 0; j < 4; j++)                                            \
            _Pragma("unroll")                                                  \
            for (int f = 0; f < 4; f++) acc[i][j][f] = 0.f;                    \
    const int NC = K >> 6;                                                     \
    {                                                                          \
        const uint32_t ab = sbase, wb = sbase + 9216u * 2u;                    \
        _Pragma("unroll")                                                      \
        for (int i = 0; i < 4; i++) {                                          \
            const int fi = tid + i * 256;                                      \
            const int row = fi >> 3, seg = fi & 7;                             \
            const uint32_t off = (uint32_t)(row * 72 + seg * 8) * 2u;          \
            cp16(ab + off, Ag + (size_t)row * K + seg * 8);                    \
            cp16(wb + off, Wg + (size_t)row * K + seg * 8);                    \
        }                                                                      \
        asm volatile("cp.async.commit_group;" ::: "memory");                   \
    }                                                                          \
    for (int c = 0; c < NC; c++) {                                             \
        if (c + 1 < NC) {                                                      \
            const uint32_t st = (uint32_t)((c + 1) & 1) * 18432u * 2u;         \
            const uint32_t ab = sbase + st, wb = sbase + st + 9216u * 2u;      \
            const int kn = (c + 1) << 6;                                       \
            _Pragma("unroll")                                                  \
            for (int i = 0; i < 4; i++) {                                      \
                const int fi = tid + i * 256;                                  \
                const int row = fi >> 3, seg = fi & 7;                         \
                const uint32_t off = (uint32_t)(row * 72 + seg * 8) * 2u;      \
                cp16(ab + off, Ag + (size_t)row * K + kn + seg * 8);           \
                cp16(wb + off, Wg + (size_t)row * K + kn + seg * 8);           \
            }                                                                  \
            asm volatile("cp.async.commit_group;" ::: "memory");               \
            asm volatile("cp.async.wait_group 1;" ::: "memory");               \
        } else {                                                               \
            asm volatile("cp.async.wait_group 0;" ::: "memory");               \
        }                                                                      \
        __syncthreads();                                                       \
        const __half* As = swh + (c & 1) * 18432;                              \
        const __half* Ws = As + 9216;                                          \
        _Pragma("unroll")                                                      \
        for (int ks = 0; ks < 4; ks++) {                                       \
            const int k0 = ks * 16;                                            \
            uint32_t af[4][4];                                                 \
            _Pragma("unroll")                                                  \
            for (int mt = 0; mt < 4; mt++) {                                   \
                const int r = wm * 64 + mt * 16 + gid;                         \
                af[mt][0] = *(const uint32_t*)&As[ r      * 72 + k0 + 2*tig    ];\
                af[mt][1] = *(const uint32_t*)&As[(r + 8) * 72 + k0 + 2*tig    ];\
                af[mt][2] = *(const uint32_t*)&As[ r      * 72 + k0 + 2*tig + 8];\
                af[mt][3] = *(const uint32_t*)&As[(r + 8) * 72 + k0 + 2*tig + 8];\
            }                                                                  \
            uint32_t bf[4][2];                                                 \
            _Pragma("unroll")                                                  \
            for (int nt = 0; nt < 4; nt++) {                                   \
                const int n = wn * 32 + nt * 8 + gid;                          \
                bf[nt][0] = *(const uint32_t*)&Ws[n * 72 + k0 + 2*tig    ];    \
                bf[nt][1] = *(const uint32_t*)&Ws[n * 72 + k0 + 2*tig + 8];    \
            }                                                                  \
            _Pragma("unroll")                                                  \
            for (int mt = 0; mt < 4; mt++)                                     \
                _Pragma("unroll")                                              \
                for (int nt = 0; nt < 4; nt++)                                 \
                    mma_f16(acc[mt][nt], af[mt], bf[nt]);                      \
        }                                                                      \
        __syncthreads();                                                       \
    }

// ---- fused QKV projection: q/k -> (B,H,S,D) fp16; v -> (B,H,D,S) fp16 -----
__global__ __launch_bounds__(256, 2)
void hgemm_qkv(const __half* __restrict__ A, const __half* __restrict__ Wall,
               const float* __restrict__ bq, const float* __restrict__ bk,
               const float* __restrict__ bv, __half* __restrict__ Call, int K)
{
    extern __shared__ __align__(16) char smemraw[];
    __half* swh = (__half*)smemraw;
    const uint32_t sbase = smem_u32(swh);
    const int tid  = threadIdx.x;
    const int wid  = tid >> 5;
    const int lane = tid & 31;
    const int gid  = lane >> 2;
    const int tig  = lane & 3;
    const int wm   = wid >> 2;
    const int wn   = wid & 3;
    const int z    = blockIdx.z;

    const __half* Ag = A + (size_t)blockIdx.y * 128 * K;
    const __half* Wg = Wall + (size_t)z * EMB * EMB + (size_t)blockIdx.x * 128 * K;
    const float* bias = (z == 0) ? bq : (z == 1) ? bk : bv;
    __half* C = Call + (size_t)z * HSZ;
    const float scale = (z == 0) ? 0.125f * LOG2E : 1.f;

    HGEMM_BODY(Ag, Wg)

    if (z < 2) {
        #pragma unroll
        for (int mt = 0; mt < 4; mt++) {
            #pragma unroll
            for (int nt = 0; nt < 4; nt++) {
                const int n = blockIdx.x * 128 + wn * 32 + nt * 8 + tig * 2;
                const float b0 = bias[n], b1 = bias[n + 1];
                #pragma unroll
                for (int half_ = 0; half_ < 2; half_++) {
                    const int m = blockIdx.y * 128 + wm * 64 + mt * 16 + gid + half_ * 8;
                    const float vx = (acc[mt][nt][half_ * 2 + 0] + b0) * scale;
                    const float vy = (acc[mt][nt][half_ * 2 + 1] + b1) * scale;
                    const int s = m >> 1, b = m & 1;
                    const int h = n >> 6, d = n & 63;
                    __half2 hv = __floats2half2_rn(vx, vy);
                    *(uint32_t*)(C + (((size_t)(b * NH + h)) * S_LEN + s) * HD + d) = h2u(hv);
                }
            }
        }
    } else {
        // V: stage [n_local][m_local] (pad 136) in smem, then coalesced
        // transposed stores to (B,H,D,S).
        __half* ts = swh;
        #pragma unroll
        for (int mt = 0; mt < 4; mt++) {
            #pragma unroll
            for (int nt = 0; nt < 4; nt++) {
                const int nl = wn * 32 + nt * 8 + tig * 2;
                const int n  = blockIdx.x * 128 + nl;
                const float b0 = bias[n], b1 = bias[n + 1];
                #pragma unroll
                for (int half_ = 0; half_ < 2; half_++) {
                    const int ml = wm * 64 + mt * 16 + gid + half_ * 8;
                    ts[ nl      * 136 + ml] = __float2half_rn(acc[mt][nt][half_ * 2 + 0] + b0);
                    ts[(nl + 1) * 136 + ml] = __float2half_rn(acc[mt][nt][half_ * 2 + 1] + b1);
                }
            }
        }
        __syncthreads();
        // rows: 128 n-local x 2 batches; warp handles 2 rows per iter
        // (lanes 0-15 row A, 16-31 row B); 16 lanes x 4 halves = 64 s values.
        #pragma unroll 1
        for (int it = 0; it < 16; it++) {
            const int gr = it * 16 + wid * 2 + (lane >> 4);   // 0..255
            const int nl = gr >> 1, b = gr & 1;
            const int n  = blockIdx.x * 128 + nl;
            const int h  = n >> 6, d = n & 63;
            const int sl = (lane & 15) * 4;                    // s-local 0..60
            __half2 p0 = __halves2half2(ts[nl * 136 + 2 * (sl + 0) + b],
                                        ts[nl * 136 + 2 * (sl + 1) + b]);
            __half2 p1 = __halves2half2(ts[nl * 136 + 2 * (sl + 2) + b],
                                        ts[nl * 136 + 2 * (sl + 3) + b]);
            uint2 pk = { h2u(p0), h2u(p1) };
            const int s = blockIdx.y * 64 + sl;
            *(uint2*)(C + (((size_t)(b * NH + h)) * HD + d) * S_LEN + s) = pk;
        }
    }
}

// ---- output projection: ctx fp16 @ wo fp16 -> fp32 out --------------------
__global__ __launch_bounds__(256, 2)
void hgemm_out(const __half* __restrict__ A, const __half* __restrict__ W,
               const float* __restrict__ bias, float* __restrict__ C, int K)
{
    extern __shared__ __align__(16) char smemraw[];
    __half* swh = (__half*)smemraw;
    const uint32_t sbase = smem_u32(swh);
    const int tid  = threadIdx.x;
    const int wid  = tid >> 5;
    const int lane = tid & 31;
    const int gid  = lane >> 2;
    const int tig  = lane & 3;
    const int wm   = wid >> 2;
    const int wn   = wid & 3;

    const __half* Ag = A + (size_t)blockIdx.y * 128 * K;
    const __half* Wg = W + (size_t)blockIdx.x * 128 * K;

    HGEMM_BODY(Ag, Wg)

    #pragma unroll
    for (int mt = 0; mt < 4; mt++) {
        #pragma unroll
        for (int nt = 0; nt < 4; nt++) {
            const int n = blockIdx.x * 128 + wn * 32 + nt * 8 + tig * 2;
            const float b0 = bias[n], b1 = bias[n + 1];
            #pragma unroll
            for (int half_ = 0; half_ < 2; half_++) {
                const int m = blockIdx.y * 128 + wm * 64 + mt * 16 + gid + half_ * 8;
                float2 v;
                v.x = acc[mt][nt][half_ * 2 + 0] + b0;
                v.y = acc[mt][nt][half_ * 2 + 1] + b1;
                *(float2*)(C + (size_t)m * (gridDim.x * 128) + n) = v;
            }
        }
    }
}

// =================== split-tf32 (3xMMA) GEMM + ReLU for the mask MLP =======
__global__ __launch_bounds__(256)
void mgemm_3x_relu(const float* __restrict__ A, const float* __restrict__ W,
                   const float* __restrict__ bias, float* __restrict__ C, int K)
{
    extern __shared__ __align__(16) char smemraw[];
    uint32_t* sw = (uint32_t*)smemraw;
    const uint32_t sbase = smem_u32(sw);
    const float* swf = (const float*)sw;
    const int tid  = threadIdx.x;
    const int wid  = tid >> 5;
    const int lane = tid & 31;
    const int gid  = lane >> 2;
    const int tig  = lane & 3;
    const int wm   = wid >> 2;
    const int wn   = wid & 3;

    const float* Ag = A + (size_t)blockIdx.y * 128 * K;
    const float* Wg = W + (size_t)blockIdx.x * 128 * K;

    float acc[4][4][4];
    #pragma unroll
    for (int i = 0; i < 4; i++)
        #pragma unroll
        for (int j = 0; j < 4; j++)
            #pragma unroll
            for (int f = 0; f < 4; f++) acc[i][j][f] = 0.f;

    const int NC = K >> 5;
    const int r0 = tid >> 3;
    const int sg = tid & 7;

    {
        const uint32_t ab = sbase, wb = sbase + 4608u * 4u;
        #pragma unroll
        for (int i = 0; i < 4; i++) {
            const int row = r0 + i * 32;
            const uint32_t off = (uint32_t)(row * 36 + sg * 4) * 4u;
            cp16(ab + off, Ag + (size_t)row * K + sg * 4);
            cp16(wb + off, Wg + (size_t)row * K + sg * 4);
        }
        asm volatile("cp.async.commit_group;" ::: "memory");
    }

    for (int c = 0; c < NC; c++) {
        if (c + 1 < NC) {
            const uint32_t st = (uint32_t)((c + 1) & 1) * 9216u * 4u;
            const uint32_t ab = sbase + st, wb = sbase + st + 4608u * 4u;
            const int kn = (c + 1) << 5;
            #pragma unroll
            for (int i = 0; i < 4; i++) {
                const int row = r0 + i * 32;
                const uint32_t off = (uint32_t)(row * 36 + sg * 4) * 4u;
                cp16(ab + off, Ag + (size_t)row * K + kn + sg * 4);
                cp16(wb + off, Wg + (size_t)row * K + kn + sg * 4);
            }
            asm volatile("cp.async.commit_group;" ::: "memory");
            asm volatile("cp.async.wait_group 1;" ::: "memory");
        } else {
            asm volatile("cp.async.wait_group 0;" ::: "memory");
        }
        __syncthreads();

        const float* As = swf + (c & 1) * 9216;
        const float* Ws = As + 4608;
        #pragma unroll
        for (int ks = 0; ks < 4; ks++) {
            const int k0 = ks * 8;
            uint32_t ah[4][4], al[4][4];
            #pragma unroll
            for (int mt = 0; mt < 4; mt++) {
                const int r = wm * 64 + mt * 16 + gid;
                float a0 = As[ r      * 36 + k0 + tig    ];
                float a1 = As[(r + 8) * 36 + k0 + tig    ];
                float a2 = As[ r      * 36 + k0 + tig + 4];
                float a3 = As[(r + 8) * 36 + k0 + tig + 4];
                ah[mt][0] = f2tf(a0); al[mt][0] = f2tf(a0 - __uint_as_float(ah[mt][0]));
                ah[mt][1] = f2tf(a1); al[mt][1] = f2tf(a1 - __uint_as_float(ah[mt][1]));
                ah[mt][2] = f2tf(a2); al[mt][2] = f2tf(a2 - __uint_as_float(ah[mt][2]));
                ah[mt][3] = f2tf(a3); al[mt][3] = f2tf(a3 - __uint_as_float(ah[mt][3]));
            }
            uint32_t bh_[4][2], bl_[4][2];
            #pragma unroll
            for (int nt = 0; nt < 4; nt++) {
                const int n = wn * 32 + nt * 8 + gid;
                float b0 = Ws[n * 36 + k0 + tig    ];
                float b1 = Ws[n * 36 + k0 + tig + 4];
                bh_[nt][0] = f2tf(b0); bl_[nt][0] = f2tf(b0 - __uint_as_float(bh_[nt][0]));
                bh_[nt][1] = f2tf(b1); bl_[nt][1] = f2tf(b1 - __uint_as_float(bh_[nt][1]));
            }
            #pragma unroll
            for (int mt = 0; mt < 4; mt++)
                #pragma unroll
                for (int nt = 0; nt < 4; nt++) {
                    mma_tf32(acc[mt][nt], al[mt], bh_[nt]);
                    mma_tf32(acc[mt][nt], ah[mt], bl_[nt]);
                    mma_tf32(acc[mt][nt], ah[mt], bh_[nt]);
                }
        }
        __syncthreads();
    }

    #pragma unroll
    for (int mt = 0; mt < 4; mt++) {
        #pragma unroll
        for (int nt = 0; nt < 4; nt++) {
            const int n = blockIdx.x * 128 + wn * 32 + nt * 8 + tig * 2;
            const float b0 = bias[n], b1 = bias[n + 1];
            #pragma unroll
            for (int half_ = 0; half_ < 2; half_++) {
                const int m = blockIdx.y * 128 + wm * 64 + mt * 16 + gid + half_ * 8;
                float2 v;
                v.x = fmaxf(acc[mt][nt][half_ * 2 + 0] + b0, 0.f);
                v.y = fmaxf(acc[mt][nt][half_ * 2 + 1] + b1, 0.f);
                *(float2*)(C + (size_t)m * (gridDim.x * 128) + n) = v;
            }
        }
    }
}

// =================== fp16 tensor-core flash attention (unchanged R12) ======
__global__ __launch_bounds__(256, 2)
void flash_h(const __half* __restrict__ Q, const __half* __restrict__ Kg,
             const __half* __restrict__ Vg, const float* __restrict__ gate,
             __half* __restrict__ ctx)
{
    extern __shared__ __align__(16) char smemraw[];
    __half* swh = (__half*)smemraw;
    const uint32_t sbase = smem_u32(swh);
    const int tid  = threadIdx.x;
    const int wid  = tid >> 5;
    const int lane = tid & 31;
    const int gid  = lane >> 2;
    const int tig  = lane & 3;
    const int bh   = blockIdx.y;
    const int b    = bh >> 4, h = bh & 15;
    const int q0   = blockIdx.x * 128;

    const __half* Qt = Q  + ((size_t)bh * S_LEN + q0) * HD;
    const __half* Kb = Kg + (size_t)bh * S_LEN * HD;
    const __half* Vb = Vg + (size_t)bh * HD * S_LEN;

    #pragma unroll
    for (int i = 0; i < 4; i++) {
        const int fi = tid + i * 256;
        const int r = fi >> 3, seg = fi & 7;
        uint4 v = *(const uint4*)(Qt + r * 64 + seg * 8);
        *(uint4*)(swh + r * 72 + seg * 8) = v;
    }
    __syncthreads();
    uint32_t qa[4][4];
    {
        const int r0q = wid * 16 + gid;
        #pragma unroll
        for (int ks = 0; ks < 4; ks++) {
            const int k0 = ks * 16;
            qa[ks][0] = *(const uint32_t*)&swh[ r0q      * 72 + k0 + 2*tig    ];
            qa[ks][1] = *(const uint32_t*)&swh[(r0q + 8) * 72 + k0 + 2*tig    ];
            qa[ks][2] = *(const uint32_t*)&swh[ r0q      * 72 + k0 + 2*tig + 8];
            qa[ks][3] = *(const uint32_t*)&swh[(r0q + 8) * 72 + k0 + 2*tig + 8];
        }
    }
    __syncthreads();

    #pragma unroll 1
    for (int t = 0; t < 2; t++) {
        const uint32_t kb = sbase + (uint32_t)t * 9216u * 2u;
        const uint32_t vb = kb + 4608u * 2u;
        const __half* Ksrc = Kb + (size_t)t * 64 * 64;
        const __half* Vsrc = Vb + (size_t)t * 64;
        #pragma unroll
        for (int i = 0; i < 4; i++) {
            const int fi = tid + i * 256;
            const int half_sel = fi >> 9;
            const int j = fi & 511;
            const int r = j >> 3, seg = j & 7;
            if (half_sel == 0)
                cp16(kb + (uint32_t)(r * 72 + seg * 8) * 2u, Ksrc + r * 64 + seg * 8);
            else
                cp16(vb + (uint32_t)(r * 72 + seg * 8) * 2u, Vsrc + (size_t)r * S_LEN + seg * 8);
        }
        asm volatile("cp.async.commit_group;" ::: "memory");
    }

    float miA = -INFINITY, miB = -INFINITY, liA = 0.f, liB = 0.f;
    float oa[8][4];
    #pragma unroll
    for (int nt = 0; nt < 8; nt++)
        #pragma unroll
        for (int f = 0; f < 4; f++) oa[nt][f] = 0.f;

    const int NT = S_LEN / 64;
    for (int t = 0; t < NT; t++) {
        if (t < NT - 2) asm volatile("cp.async.wait_group 1;" ::: "memory");
        else            asm volatile("cp.async.wait_group 0;" ::: "memory");
        __syncthreads();
        const __half* Ks = swh + (t & 1) * 9216;
        const __half* Vs = Ks + 4608;

        float sa[8][4];
        #pragma unroll
        for (int nt = 0; nt < 8; nt++)
            #pragma unroll
            for (int f = 0; f < 4; f++) sa[nt][f] = 0.f;
        #pragma unroll
        for (int ks = 0; ks < 4; ks++) {
            const int k0 = ks * 16;
            #pragma unroll
            for (int nt = 0; nt < 8; nt++) {
                uint32_t bf[2];
                bf[0] = *(const uint32_t*)&Ks[(nt * 8 + gid) * 72 + k0 + 2*tig    ];
                bf[1] = *(const uint32_t*)&Ks[(nt * 8 + gid) * 72 + k0 + 2*tig + 8];
                mma_f16(sa[nt], qa[ks], bf);
            }
        }

        float rmA = -INFINITY, rmB = -INFINITY;
        #pragma unroll
        for (int nt = 0; nt < 8; nt++) {
            rmA = fmaxf(rmA, fmaxf(sa[nt][0], sa[nt][1]));
            rmB = fmaxf(rmB, fmaxf(sa[nt][2], sa[nt][3]));
        }
        rmA = fmaxf(rmA, __shfl_xor_sync(0xffffffffu, rmA, 1));
        rmA = fmaxf(rmA, __shfl_xor_sync(0xffffffffu, rmA, 2));
        rmB = fmaxf(rmB, __shfl_xor_sync(0xffffffffu, rmB, 1));
        rmB = fmaxf(rmB, __shfl_xor_sync(0xffffffffu, rmB, 2));

        const float mAn = fmaxf(miA, rmA);
        const float mBn = fmaxf(miB, rmB);
        const float aA  = exp2f(miA - mAn);
        const float aB  = exp2f(miB - mBn);
        miA = mAn; miB = mBn;

        float rsA = 0.f, rsB = 0.f;
        #pragma unroll
        for (int nt = 0; nt < 8; nt++) {
            sa[nt][0] = exp2f(sa[nt][0] - mAn);
            sa[nt][1] = exp2f(sa[nt][1] - mAn);
            sa[nt][2] = exp2f(sa[nt][2] - mBn);
            sa[nt][3] = exp2f(sa[nt][3] - mBn);
            rsA += sa[nt][0] + sa[nt][1];
            rsB += sa[nt][2] + sa[nt][3];
        }
        rsA += __shfl_xor_sync(0xffffffffu, rsA, 1);
        rsA += __shfl_xor_sync(0xffffffffu, rsA, 2);
        rsB += __shfl_xor_sync(0xffffffffu, rsB, 1);
        rsB += __shfl_xor_sync(0xffffffffu, rsB, 2);
        liA = liA * aA + rsA;
        liB = liB * aB + rsB;
        #pragma unroll
        for (int nt = 0; nt < 8; nt++) {
            oa[nt][0] *= aA; oa[nt][1] *= aA;
            oa[nt][2] *= aB; oa[nt][3] *= aB;
        }

        #pragma unroll
        for (int kk = 0; kk < 4; kk++) {
            uint32_t af[4];
            af[0] = h2u(__floats2half2_rn(sa[2*kk  ][0], sa[2*kk  ][1]));
            af[1] = h2u(__floats2half2_rn(sa[2*kk  ][2], sa[2*kk  ][3]));
            af[2] = h2u(__floats2half2_rn(sa[2*kk+1][0], sa[2*kk+1][1]));
            af[3] = h2u(__floats2half2_rn(sa[2*kk+1][2], sa[2*kk+1][3]));
            const int k0 = kk * 16;
            #pragma unroll
            for (int nt = 0; nt < 8; nt++) {
                uint32_t bf[2];
                bf[0] = *(const uint32_t*)&Vs[(nt * 8 + gid) * 72 + k0 + 2*tig    ];
                bf[1] = *(const uint32_t*)&Vs[(nt * 8 + gid) * 72 + k0 + 2*tig + 8];
                mma_f16(oa[nt], af, bf);
            }
        }
        __syncthreads();

        if (t + 2 < NT) {
            const uint32_t kb = sbase + (uint32_t)(t & 1) * 9216u * 2u;
            const uint32_t vb = kb + 4608u * 2u;
            const __half* Ksrc = Kb + (size_t)(t + 2) * 64 * 64;
            const __half* Vsrc = Vb + (size_t)(t + 2) * 64;
            #pragma unroll
            for (int i = 0; i < 4; i++) {
                const int fi = tid + i * 256;
                const int half_sel = fi >> 9;
                const int j = fi & 511;
                const int r = j >> 3, seg = j & 7;
                if (half_sel == 0)
                    cp16(kb + (uint32_t)(r * 72 + seg * 8) * 2u, Ksrc + r * 64 + seg * 8);
                else
                    cp16(vb + (uint32_t)(r * 72 + seg * 8) * 2u, Vsrc + (size_t)r * S_LEN + seg * 8);
            }
            asm volatile("cp.async.commit_group;" ::: "memory");
        }
    }

    const int sA = q0 + wid * 16 + gid;
    const int sB = sA + 8;
    const float gA = gate[(size_t)bh * S_LEN + sA];
    const float gB = gate[(size_t)bh * S_LEN + sB];
    const float invA = gA / liA;
    const float invB = gB / liB;
    #pragma unroll
    for (int nt = 0; nt < 8; nt++) {
        const int col = h * 64 + nt * 8 + tig * 2;
        __half2 va = __floats2half2_rn(oa[nt][0] * invA, oa[nt][1] * invA);
        __half2 vb = __floats2half2_rn(oa[nt][2] * invB, oa[nt][3] * invB);
        *(uint32_t*)(ctx + ((size_t)sA * BATCH + b) * EMB + col) = h2u(va);
        *(uint32_t*)(ctx + ((size_t)sB * BATCH + b) * EMB + col) = h2u(vb);
    }
}

// ---------------- fold head_sig into inf2 ---------------------------------
__global__ void combine_sig(const float* __restrict__ hs,
                            const float* __restrict__ w2,
                            const float* __restrict__ b2,
                            float* __restrict__ mcomb,
                            float* __restrict__ cbias)
{
    const int idx = blockIdx.x * blockDim.x + threadIdx.x;
    if (idx < NH * HID) {
        const int h = idx / HID, k = idx % HID;
        float a = 0.f;
        #pragma unroll
        for (int j = 0; j < 64; j++) a += hs[h*64 + j] * w2[j*HID + k];
        mcomb[idx] = a;
    }
    if (idx < NH) {
        float a = 0.f;
        #pragma unroll
        for (int j = 0; j < 64; j++) a += hs[idx*64 + j] * b2[j];
        cbias[idx] = a;
    }
}

// ---------------- head scores + top-12 mask (float4 loads) ----------------
__global__ __launch_bounds__(256)
void head_scores(const float* __restrict__ t1, const float* __restrict__ mcomb,
                 const float* __restrict__ cbias, float* __restrict__ mask)
{
    const int warp = (blockIdx.x * blockDim.x + threadIdx.x) >> 5;
    const int lane = threadIdx.x & 31;
    if (warp >= MROWS) return;
    const float4* row4 = (const float4*)(t1 + (size_t)warp * HID);
    const float4* mc4  = (const float4*)mcomb;

    float acc[NH];
    #pragma unroll
    for (int h = 0; h < NH; h++) acc[h] = 0.f;
    #pragma unroll
    for (int it = 0; it < 4; it++) {
        const int k4 = it * 32 + lane;
        const float4 a = row4[k4];
        #pragma unroll
        for (int h = 0; h < NH; h++) {
            const float4 m = mc4[h * (HID/4) + k4];
            acc[h] += a.x*m.x + a.y*m.y + a.z*m.z + a.w*m.w;
        }
    }
    #pragma unroll
    for (int h = 0; h < NH; h++)
        #pragma unroll
        for (int off = 16; off > 0; off >>= 1)
            acc[h] += __shfl_xor_sync(0xffffffffu, acc[h], off);

    if (lane == 0) {
        float sc[NH], tmp[NH];
        #pragma unroll
        for (int h = 0; h < NH; h++) { sc[h] = acc[h] + cbias[h]; tmp[h] = sc[h]; }
        float thr = 0.f;
        for (int it = 0; it < NH - 4; it++) {
            int bi = 0; float bv = tmp[0];
            #pragma unroll
            for (int h = 1; h < NH; h++) if (tmp[h] > bv) { bv = tmp[h]; bi = h; }
            thr = bv; tmp[bi] = -INFINITY;
        }
        const int s = warp >> 1, b = warp & 1;
        #pragma unroll
        for (int h = 0; h < NH; h++)
            mask[((size_t)(b * NH + h)) * S_LEN + s] = (sc[h] >= thr) ? 1.f : 0.f;
    }
}

// ---------------------------------------------------------------------------
extern "C" void kernel_launch(void* const* d_in, const int* in_sizes, int n_in,
                              void* d_out, int out_size)
{
    const float* query   = (const float*)d_in[0];
    const float* q_w     = (const float*)d_in[1];
    const float* q_b     = (const float*)d_in[2];
    const float* k_w     = (const float*)d_in[3];
    const float* k_b     = (const float*)d_in[4];
    const float* v_w     = (const float*)d_in[5];
    const float* v_b     = (const float*)d_in[6];
    const float* out_w   = (const float*)d_in[7];
    const float* out_b   = (const float*)d_in[8];
    const float* inf1_w  = (const float*)d_in[9];
    const float* inf1_b  = (const float*)d_in[10];
    const float* inf2_w  = (const float*)d_in[11];
    const float* inf2_b  = (const float*)d_in[12];
    const float* head_sig= (const float*)d_in[13];
    float* out = (float*)d_out;

    __half *pqkv, *pctx, *pqh, *pwqkv, *pwo;
    float *pt1, *pmc, *pcb, *pmask;
    cudaGetSymbolAddress((void**)&pqkv, g_qkv);
    cudaGetSymbolAddress((void**)&pctx, g_ctx);
    cudaGetSymbolAddress((void**)&pt1,  g_t1);
    cudaGetSymbolAddress((void**)&pmc,  g_mcomb);
    cudaGetSymbolAddress((void**)&pcb,  g_cbias);
    cudaGetSymbolAddress((void**)&pmask,g_mask);
    cudaGetSymbolAddress((void**)&pqh,  g_qh);
    cudaGetSymbolAddress((void**)&pwqkv,g_wqkv);
    cudaGetSymbolAddress((void**)&pwo,  g_wo);

    const int HGS = 73728;   // fp16 GEMM: 2 stages x 18432 halves
    const int GS3 = 73728;   // 3x-relu fp32 layout
    const int FS  = 36864;   // flash fp16
    cudaFuncSetAttribute(hgemm_qkv, cudaFuncAttributeMaxDynamicSharedMemorySize, HGS);
    cudaFuncSetAttribute(hgemm_out, cudaFuncAttributeMaxDynamicSharedMemorySize, HGS);
    cudaFuncSetAttribute(mgemm_3x_relu, cudaFuncAttributeMaxDynamicSharedMemorySize, GS3);
    cudaFuncSetAttribute(flash_h, cudaFuncAttributeMaxDynamicSharedMemorySize, FS);

    // side stream + fork/join events (created per call; never destroyed so
    // the captured graph's references stay valid)
    cudaStream_t s2;
    cudaEvent_t eFork, eJoin;
    cudaStreamCreateWithFlags(&s2, cudaStreamNonBlocking);
    cudaEventCreateWithFlags(&eFork, cudaEventDisableTiming);
    cudaEventCreateWithFlags(&eJoin, cudaEventDisableTiming);

    cudaEventRecord(eFork, 0);
    cudaStreamWaitEvent(s2, eFork, 0);

    // --- side stream: combine_sig -> 3x MLP -> head_scores -----------------
    combine_sig<<<(NH*HID + 255)/256, 256, 0, s2>>>(head_sig, inf2_w, inf2_b,
                                                    pmc, pcb);
    {
        dim3 g(HID/128, MROWS/128);
        mgemm_3x_relu<<<g, 256, GS3, s2>>>(query, inf1_w, inf1_b, pt1, EMB);
    }
    head_scores<<<MROWS/8, 256, 0, s2>>>(pt1, pmc, pcb, pmask);
    cudaEventRecord(eJoin, s2);

    // --- main stream: fp16 convert -> QKV -----------------------------------
    {
        const int total = NQ4 + 4 * NW4;
        round_all<<<(total + 255)/256, 256>>>(query, q_w, k_w, v_w, out_w,
                                              pqh, pwqkv, pwo);
    }
    {
        dim3 g(EMB/128, MROWS/128, 3);
        hgemm_qkv<<<g, 256, HGS>>>(pqh, pwqkv, q_b, k_b, v_b, pqkv, EMB);
    }

    cudaStreamWaitEvent(0, eJoin, 0);

    // --- flash attention (fp16) -> ctx fp16 ---------------------------------
    {
        dim3 g(S_LEN/128, BATCH*NH);
        flash_h<<<g, 256, FS>>>(pqkv, pqkv + HSZ, pqkv + 2*HSZ, pmask, pctx);
    }
    // --- output projection ---------------------------------------------------
    {
        dim3 g(EMB/128, MROWS/128);
        hgemm_out<<<g, 256, HGS>>>(pctx, pwo, out_b, out, EMB);
    }
    (void)in_sizes; (void)n_in; (void)out_size;
}

// round 14
// speedup vs baseline: 1.5880x; 1.0160x over previous
#include <cuda_runtime.h>
#include <cuda_fp16.h>
#include <math.h>
#include <stdint.h>

#define S_LEN 2048
#define BATCH 2
#define EMB   1024
#define NH    16
#define HD    64
#define HID   512
#define MROWS (S_LEN*BATCH)   // 4096
#define HSZ   (BATCH*NH*S_LEN*HD)
#define LOG2E 1.4426950408889634f

// ---------------- scratch (static device globals; no allocation) ----------
__device__ __align__(16) __half g_qkv[3*HSZ];      // q|k fp16 (B,H,S,D); v fp16 (B,H,D,S)
__device__ __align__(16) __half g_ctx[MROWS*EMB];  // (S,B,E) fp16
__device__ float  g_t1 [MROWS*HID];
__device__ float  g_mcomb[NH*HID];
__device__ float  g_cbias[NH];
__device__ float  g_mask[BATCH*NH*S_LEN];
__device__ __align__(16) __half g_qh  [MROWS*EMB]; // fp16 query
__device__ __align__(16) __half g_wqkv[3*EMB*EMB]; // fp16 q_w|k_w|v_w
__device__ __align__(16) __half g_wo  [EMB*EMB];   // fp16 out_w

// =================== helpers ===============================================
__device__ __forceinline__ uint32_t f2tf(float x) {
    uint32_t r; asm("cvt.rna.tf32.f32 %0, %1;" : "=r"(r) : "f"(x)); return r;
}
__device__ __forceinline__ uint32_t smem_u32(const void* p) {
    uint32_t a;
    asm("{ .reg .u64 t; cvta.to.shared.u64 t, %1; cvt.u32.u64 %0, t; }"
        : "=r"(a) : "l"(p));
    return a;
}
__device__ __forceinline__ void cp16(uint32_t saddr, const void* g) {
    asm volatile("cp.async.cg.shared.global [%0], [%1], 16;"
                 :: "r"(saddr), "l"(g) : "memory");
}
__device__ __forceinline__ void mma_f16(float* d, const uint32_t* a, const uint32_t* b) {
    asm volatile(
        "mma.sync.aligned.m16n8k16.row.col.f32.f16.f16.f32 "
        "{%0,%1,%2,%3}, {%4,%5,%6,%7}, {%8,%9}, {%0,%1,%2,%3};"
        : "+f"(d[0]), "+f"(d[1]), "+f"(d[2]), "+f"(d[3])
        : "r"(a[0]), "r"(a[1]), "r"(a[2]), "r"(a[3]), "r"(b[0]), "r"(b[1]));
}
__device__ __forceinline__ void mma_tf32(float* d, const uint32_t* a, const uint32_t* b) {
    asm volatile(
        "mma.sync.aligned.m16n8k8.row.col.f32.tf32.tf32.f32 "
        "{%0,%1,%2,%3}, {%4,%5,%6,%7}, {%8,%9}, {%0,%1,%2,%3};"
        : "+f"(d[0]), "+f"(d[1]), "+f"(d[2]), "+f"(d[3])
        : "r"(a[0]), "r"(a[1]), "r"(a[2]), "r"(a[3]), "r"(b[0]), "r"(b[1]));
}
__device__ __forceinline__ void ldsm4(uint32_t* r, uint32_t addr) {
    asm volatile("ldmatrix.sync.aligned.m8n8.x4.shared.b16 {%0,%1,%2,%3}, [%4];"
                 : "=r"(r[0]), "=r"(r[1]), "=r"(r[2]), "=r"(r[3]) : "r"(addr));
}
__device__ __forceinline__ uint32_t h2u(__half2 h) {
    return *(uint32_t*)&h;
}

// ---------------- fused fp16 conversion of query + 4 weight matrices ------
#define NQ4 (MROWS*EMB/4)      // 1048576
#define NW4 (EMB*EMB/4)        // 262144 = 1<<18
__global__ void round_all(const float* __restrict__ q,
                          const float* __restrict__ wq,
                          const float* __restrict__ wk,
                          const float* __restrict__ wv,
                          const float* __restrict__ wo,
                          __half* __restrict__ dq,
                          __half* __restrict__ dwqkv,
                          __half* __restrict__ dwo)
{
    const int i = blockIdx.x * blockDim.x + threadIdx.x;
    const float4* src; __half* dst; int off;
    if (i < NQ4) { src = (const float4*)q; dst = dq; off = i; }
    else {
        const int j = i - NQ4;
        const int z = j >> 18;
        off = j & (NW4 - 1);
        if      (z == 0) { src = (const float4*)wq; dst = dwqkv; }
        else if (z == 1) { src = (const float4*)wk; dst = dwqkv + 4*NW4; }
        else if (z == 2) { src = (const float4*)wv; dst = dwqkv + 8*NW4; }
        else             { src = (const float4*)wo; dst = dwo; }
    }
    float4 v = src[off];
    __half2 lo = __floats2half2_rn(v.x, v.y);
    __half2 hi = __floats2half2_rn(v.z, v.w);
    uint2 pk = { h2u(lo), h2u(hi) };
    *(uint2*)(dst + (size_t)off * 4) = pk;
}

// =================== cp.async pipelined fp16 GEMM core =====================
// K-chunks of 64 halves; row pad 72 halves. Stage: A 9216 halves @0, W @9216;
// stage stride 18432 halves (36864 B). 2 stages = 73728 B.
#define HGEMM_BODY(Ag, Wg)                                                     \
    float acc[4][4][4];                                                        \
    _Pragma("unroll")                                                          \
    for (int i = 0; i < 4; i++)                                                \
        _Pragma("unroll")                                                      \
        for (int j = 0; j < 4; j++)                                            \
            _Pragma("unroll")                                                  \
            for (int f = 0; f < 4; f++) acc[i][j][f] = 0.f;                    \
    const int NC = K >> 6;                                                     \
    {                                                                          \
        const uint32_t ab = sbase, wb = sbase + 9216u * 2u;                    \
        _Pragma("unroll")                                                      \
        for (int i = 0; i < 4; i++) {                                          \
            const int fi = tid + i * 256;                                      \
            const int row = fi >> 3, seg = fi & 7;                             \
            const uint32_t off = (uint32_t)(row * 72 + seg * 8) * 2u;          \
            cp16(ab + off, Ag + (size_t)row * K + seg * 8);                    \
            cp16(wb + off, Wg + (size_t)row * K + seg * 8);                    \
        }                                                                      \
        asm volatile("cp.async.commit_group;" ::: "memory");                   \
    }                                                                          \
    for (int c = 0; c < NC; c++) {                                             \
        if (c + 1 < NC) {                                                      \
            const uint32_t st = (uint32_t)((c + 1) & 1) * 18432u * 2u;         \
            const uint32_t ab = sbase + st, wb = sbase + st + 9216u * 2u;      \
            const int kn = (c + 1) << 6;                                       \
            _Pragma("unroll")                                                  \
            for (int i = 0; i < 4; i++) {                                      \
                const int fi = tid + i * 256;                                  \
                const int row = fi >> 3, seg = fi & 7;                         \
                const uint32_t off = (uint32_t)(row * 72 + seg * 8) * 2u;      \
                cp16(ab + off, Ag + (size_t)row * K + kn + seg * 8);           \
                cp16(wb + off, Wg + (size_t)row * K + kn + seg * 8);           \
            }                                                                  \
            asm volatile("cp.async.commit_group;" ::: "memory");               \
            asm volatile("cp.async.wait_group 1;" ::: "memory");               \
        } else {                                                               \
            asm volatile("cp.async.wait_group 0;" ::: "memory");               \
        }                                                                      \
        __syncthreads();                                                       \
        const __half* As = swh + (c & 1) * 18432;                              \
        const __half* Ws = As + 9216;                                          \
        _Pragma("unroll")                                                      \
        for (int ks = 0; ks < 4; ks++) {                                       \
            const int k0 = ks * 16;                                            \
            uint32_t af[4][4];                                                 \
            _Pragma("unroll")                                                  \
            for (int mt = 0; mt < 4; mt++) {                                   \
                const int r = wm * 64 + mt * 16 + gid;                         \
                af[mt][0] = *(const uint32_t*)&As[ r      * 72 + k0 + 2*tig    ];\
                af[mt][1] = *(const uint32_t*)&As[(r + 8) * 72 + k0 + 2*tig    ];\
                af[mt][2] = *(const uint32_t*)&As[ r      * 72 + k0 + 2*tig + 8];\
                af[mt][3] = *(const uint32_t*)&As[(r + 8) * 72 + k0 + 2*tig + 8];\
            }                                                                  \
            uint32_t bf[4][2];                                                 \
            _Pragma("unroll")                                                  \
            for (int nt = 0; nt < 4; nt++) {                                   \
                const int n = wn * 32 + nt * 8 + gid;                          \
                bf[nt][0] = *(const uint32_t*)&Ws[n * 72 + k0 + 2*tig    ];    \
                bf[nt][1] = *(const uint32_t*)&Ws[n * 72 + k0 + 2*tig + 8];    \
            }                                                                  \
            _Pragma("unroll")                                                  \
            for (int mt = 0; mt < 4; mt++)                                     \
                _Pragma("unroll")                                              \
                for (int nt = 0; nt < 4; nt++)                                 \
                    mma_f16(acc[mt][nt], af[mt], bf[nt]);                      \
        }                                                                      \
        __syncthreads();                                                       \
    }

// ---- fused QKV projection: q/k -> (B,H,S,D) fp16; v -> (B,H,D,S) fp16 -----
__global__ __launch_bounds__(256, 2)
void hgemm_qkv(const __half* __restrict__ A, const __half* __restrict__ Wall,
               const float* __restrict__ bq, const float* __restrict__ bk,
               const float* __restrict__ bv, __half* __restrict__ Call, int K)
{
    extern __shared__ __align__(16) char smemraw[];
    __half* swh = (__half*)smemraw;
    const uint32_t sbase = smem_u32(swh);
    const int tid  = threadIdx.x;
    const int wid  = tid >> 5;
    const int lane = tid & 31;
    const int gid  = lane >> 2;
    const int tig  = lane & 3;
    const int wm   = wid >> 2;
    const int wn   = wid & 3;
    const int z    = blockIdx.z;

    const __half* Ag = A + (size_t)blockIdx.y * 128 * K;
    const __half* Wg = Wall + (size_t)z * EMB * EMB + (size_t)blockIdx.x * 128 * K;
    const float* bias = (z == 0) ? bq : (z == 1) ? bk : bv;
    __half* C = Call + (size_t)z * HSZ;
    const float scale = (z == 0) ? 0.125f * LOG2E : 1.f;

    HGEMM_BODY(Ag, Wg)

    if (z < 2) {
        #pragma unroll
        for (int mt = 0; mt < 4; mt++) {
            #pragma unroll
            for (int nt = 0; nt < 4; nt++) {
                const int n = blockIdx.x * 128 + wn * 32 + nt * 8 + tig * 2;
                const float b0 = bias[n], b1 = bias[n + 1];
                #pragma unroll
                for (int half_ = 0; half_ < 2; half_++) {
                    const int m = blockIdx.y * 128 + wm * 64 + mt * 16 + gid + half_ * 8;
                    const float vx = (acc[mt][nt][half_ * 2 + 0] + b0) * scale;
                    const float vy = (acc[mt][nt][half_ * 2 + 1] + b1) * scale;
                    const int s = m >> 1, b = m & 1;
                    const int h = n >> 6, d = n & 63;
                    __half2 hv = __floats2half2_rn(vx, vy);
                    *(uint32_t*)(C + (((size_t)(b * NH + h)) * S_LEN + s) * HD + d) = h2u(hv);
                }
            }
        }
    } else {
        __half* ts = swh;
        #pragma unroll
        for (int mt = 0; mt < 4; mt++) {
            #pragma unroll
            for (int nt = 0; nt < 4; nt++) {
                const int nl = wn * 32 + nt * 8 + tig * 2;
                const int n  = blockIdx.x * 128 + nl;
                const float b0 = bias[n], b1 = bias[n + 1];
                #pragma unroll
                for (int half_ = 0; half_ < 2; half_++) {
                    const int ml = wm * 64 + mt * 16 + gid + half_ * 8;
                    ts[ nl      * 136 + ml] = __float2half_rn(acc[mt][nt][half_ * 2 + 0] + b0);
                    ts[(nl + 1) * 136 + ml] = __float2half_rn(acc[mt][nt][half_ * 2 + 1] + b1);
                }
            }
        }
        __syncthreads();
        #pragma unroll 1
        for (int it = 0; it < 16; it++) {
            const int gr = it * 16 + wid * 2 + (lane >> 4);
            const int nl = gr >> 1, b = gr & 1;
            const int n  = blockIdx.x * 128 + nl;
            const int h  = n >> 6, d = n & 63;
            const int sl = (lane & 15) * 4;
            __half2 p0 = __halves2half2(ts[nl * 136 + 2 * (sl + 0) + b],
                                        ts[nl * 136 + 2 * (sl + 1) + b]);
            __half2 p1 = __halves2half2(ts[nl * 136 + 2 * (sl + 2) + b],
                                        ts[nl * 136 + 2 * (sl + 3) + b]);
            uint2 pk = { h2u(p0), h2u(p1) };
            const int s = blockIdx.y * 64 + sl;
            *(uint2*)(C + (((size_t)(b * NH + h)) * HD + d) * S_LEN + s) = pk;
        }
    }
}

// ---- output projection: ctx fp16 @ wo fp16 -> fp32 out --------------------
__global__ __launch_bounds__(256, 2)
void hgemm_out(const __half* __restrict__ A, const __half* __restrict__ W,
               const float* __restrict__ bias, float* __restrict__ C, int K)
{
    extern __shared__ __align__(16) char smemraw[];
    __half* swh = (__half*)smemraw;
    const uint32_t sbase = smem_u32(swh);
    const int tid  = threadIdx.x;
    const int wid  = tid >> 5;
    const int lane = tid & 31;
    const int gid  = lane >> 2;
    const int tig  = lane & 3;
    const int wm   = wid >> 2;
    const int wn   = wid & 3;

    const __half* Ag = A + (size_t)blockIdx.y * 128 * K;
    const __half* Wg = W + (size_t)blockIdx.x * 128 * K;

    HGEMM_BODY(Ag, Wg)

    #pragma unroll
    for (int mt = 0; mt < 4; mt++) {
        #pragma unroll
        for (int nt = 0; nt < 4; nt++) {
            const int n = blockIdx.x * 128 + wn * 32 + nt * 8 + tig * 2;
            const float b0 = bias[n], b1 = bias[n + 1];
            #pragma unroll
            for (int half_ = 0; half_ < 2; half_++) {
                const int m = blockIdx.y * 128 + wm * 64 + mt * 16 + gid + half_ * 8;
                float2 v;
                v.x = acc[mt][nt][half_ * 2 + 0] + b0;
                v.y = acc[mt][nt][half_ * 2 + 1] + b1;
                *(float2*)(C + (size_t)m * (gridDim.x * 128) + n) = v;
            }
        }
    }
}

// =================== split-tf32 (3xMMA) GEMM + ReLU for the mask MLP =======
__global__ __launch_bounds__(256)
void mgemm_3x_relu(const float* __restrict__ A, const float* __restrict__ W,
                   const float* __restrict__ bias, float* __restrict__ C, int K)
{
    extern __shared__ __align__(16) char smemraw[];
    uint32_t* sw = (uint32_t*)smemraw;
    const uint32_t sbase = smem_u32(sw);
    const float* swf = (const float*)sw;
    const int tid  = threadIdx.x;
    const int wid  = tid >> 5;
    const int lane = tid & 31;
    const int gid  = lane >> 2;
    const int tig  = lane & 3;
    const int wm   = wid >> 2;
    const int wn   = wid & 3;

    const float* Ag = A + (size_t)blockIdx.y * 128 * K;
    const float* Wg = W + (size_t)blockIdx.x * 128 * K;

    float acc[4][4][4];
    #pragma unroll
    for (int i = 0; i < 4; i++)
        #pragma unroll
        for (int j = 0; j < 4; j++)
            #pragma unroll
            for (int f = 0; f < 4; f++) acc[i][j][f] = 0.f;

    const int NC = K >> 5;
    const int r0 = tid >> 3;
    const int sg = tid & 7;

    {
        const uint32_t ab = sbase, wb = sbase + 4608u * 4u;
        #pragma unroll
        for (int i = 0; i < 4; i++) {
            const int row = r0 + i * 32;
            const uint32_t off = (uint32_t)(row * 36 + sg * 4) * 4u;
            cp16(ab + off, Ag + (size_t)row * K + sg * 4);
            cp16(wb + off, Wg + (size_t)row * K + sg * 4);
        }
        asm volatile("cp.async.commit_group;" ::: "memory");
    }

    for (int c = 0; c < NC; c++) {
        if (c + 1 < NC) {
            const uint32_t st = (uint32_t)((c + 1) & 1) * 9216u * 4u;
            const uint32_t ab = sbase + st, wb = sbase + st + 4608u * 4u;
            const int kn = (c + 1) << 5;
            #pragma unroll
            for (int i = 0; i < 4; i++) {
                const int row = r0 + i * 32;
                const uint32_t off = (uint32_t)(row * 36 + sg * 4) * 4u;
                cp16(ab + off, Ag + (size_t)row * K + kn + sg * 4);
                cp16(wb + off, Wg + (size_t)row * K + kn + sg * 4);
            }
            asm volatile("cp.async.commit_group;" ::: "memory");
            asm volatile("cp.async.wait_group 1;" ::: "memory");
        } else {
            asm volatile("cp.async.wait_group 0;" ::: "memory");
        }
        __syncthreads();

        const float* As = swf + (c & 1) * 9216;
        const float* Ws = As + 4608;
        #pragma unroll
        for (int ks = 0; ks < 4; ks++) {
            const int k0 = ks * 8;
            uint32_t ah[4][4], al[4][4];
            #pragma unroll
            for (int mt = 0; mt < 4; mt++) {
                const int r = wm * 64 + mt * 16 + gid;
                float a0 = As[ r      * 36 + k0 + tig    ];
                float a1 = As[(r + 8) * 36 + k0 + tig    ];
                float a2 = As[ r      * 36 + k0 + tig + 4];
                float a3 = As[(r + 8) * 36 + k0 + tig + 4];
                ah[mt][0] = f2tf(a0); al[mt][0] = f2tf(a0 - __uint_as_float(ah[mt][0]));
                ah[mt][1] = f2tf(a1); al[mt][1] = f2tf(a1 - __uint_as_float(ah[mt][1]));
                ah[mt][2] = f2tf(a2); al[mt][2] = f2tf(a2 - __uint_as_float(ah[mt][2]));
                ah[mt][3] = f2tf(a3); al[mt][3] = f2tf(a3 - __uint_as_float(ah[mt][3]));
            }
            uint32_t bh_[4][2], bl_[4][2];
            #pragma unroll
            for (int nt = 0; nt < 4; nt++) {
                const int n = wn * 32 + nt * 8 + gid;
                float b0 = Ws[n * 36 + k0 + tig    ];
                float b1 = Ws[n * 36 + k0 + tig + 4];
                bh_[nt][0] = f2tf(b0); bl_[nt][0] = f2tf(b0 - __uint_as_float(bh_[nt][0]));
                bh_[nt][1] = f2tf(b1); bl_[nt][1] = f2tf(b1 - __uint_as_float(bh_[nt][1]));
            }
            #pragma unroll
            for (int mt = 0; mt < 4; mt++)
                #pragma unroll
                for (int nt = 0; nt < 4; nt++) {
                    mma_tf32(acc[mt][nt], al[mt], bh_[nt]);
                    mma_tf32(acc[mt][nt], ah[mt], bl_[nt]);
                    mma_tf32(acc[mt][nt], ah[mt], bh_[nt]);
                }
        }
        __syncthreads();
    }

    #pragma unroll
    for (int mt = 0; mt < 4; mt++) {
        #pragma unroll
        for (int nt = 0; nt < 4; nt++) {
            const int n = blockIdx.x * 128 + wn * 32 + nt * 8 + tig * 2;
            const float b0 = bias[n], b1 = bias[n + 1];
            #pragma unroll
            for (int half_ = 0; half_ < 2; half_++) {
                const int m = blockIdx.y * 128 + wm * 64 + mt * 16 + gid + half_ * 8;
                float2 v;
                v.x = fmaxf(acc[mt][nt][half_ * 2 + 0] + b0, 0.f);
                v.y = fmaxf(acc[mt][nt][half_ * 2 + 1] + b1, 0.f);
                *(float2*)(C + (size_t)m * (gridDim.x * 128) + n) = v;
            }
        }
    }
}

// =================== fp16 flash attention with ldmatrix ====================
// Q,K fp16 (B,H,S,D); V fp16 transposed (B,H,D,S). exp2 softmax.
// smem stages: K (64x72 halves) + Vt (64x72); stage stride 18432 B.
__global__ __launch_bounds__(256, 2)
void flash_h(const __half* __restrict__ Q, const __half* __restrict__ Kg,
             const __half* __restrict__ Vg, const float* __restrict__ gate,
             __half* __restrict__ ctx)
{
    extern __shared__ __align__(16) char smemraw[];
    __half* swh = (__half*)smemraw;
    const uint32_t sbase = smem_u32(swh);
    const int tid  = threadIdx.x;
    const int wid  = tid >> 5;
    const int lane = tid & 31;
    const int gid  = lane >> 2;
    const int tig  = lane & 3;
    const int bh   = blockIdx.y;
    const int b    = bh >> 4, h = bh & 15;
    const int q0   = blockIdx.x * 128;

    const __half* Qt = Q  + ((size_t)bh * S_LEN + q0) * HD;
    const __half* Kb = Kg + (size_t)bh * S_LEN * HD;
    const __half* Vb = Vg + (size_t)bh * HD * S_LEN;

    // ldmatrix lane offsets (bytes):
    const int a23 = lane >> 3, rin = lane & 7;
    // A atoms: {rows+0 klo, rows+8 klo, rows+0 khi, rows+8 khi}
    const uint32_t alane = (uint32_t)((((a23 & 1) * 8 + rin) * 72 + (a23 >> 1) * 8) * 2);
    // B atoms: {nt0 klo, nt0 khi, nt1 klo, nt1 khi}
    const uint32_t blane = (uint32_t)((((a23 >> 1) * 8 + rin) * 72 + (a23 & 1) * 8) * 2);

    // ---- stage Q (pad 72 halves) then ldmatrix the A fragments -------------
    #pragma unroll
    for (int i = 0; i < 4; i++) {
        const int fi = tid + i * 256;
        const int r = fi >> 3, seg = fi & 7;
        uint4 v = *(const uint4*)(Qt + r * 64 + seg * 8);
        *(uint4*)(swh + r * 72 + seg * 8) = v;
    }
    __syncthreads();
    uint32_t qa[4][4];
    {
        const uint32_t qaddr = sbase + (uint32_t)(wid * 16) * 144u + alane;
        #pragma unroll
        for (int ks = 0; ks < 4; ks++)
            ldsm4(qa[ks], qaddr + (uint32_t)(ks * 32));
    }
    __syncthreads();

    // ---- issue first two K/V tiles -----------------------------------------
    #pragma unroll 1
    for (int t = 0; t < 2; t++) {
        const uint32_t kb = sbase + (uint32_t)t * 18432u;
        const uint32_t vb = kb + 9216u;
        const __half* Ksrc = Kb + (size_t)t * 64 * 64;
        const __half* Vsrc = Vb + (size_t)t * 64;
        #pragma unroll
        for (int i = 0; i < 4; i++) {
            const int fi = tid + i * 256;
            const int half_sel = fi >> 9;
            const int j = fi & 511;
            const int r = j >> 3, seg = j & 7;
            if (half_sel == 0)
                cp16(kb + (uint32_t)(r * 72 + seg * 8) * 2u, Ksrc + r * 64 + seg * 8);
            else
                cp16(vb + (uint32_t)(r * 72 + seg * 8) * 2u, Vsrc + (size_t)r * S_LEN + seg * 8);
        }
        asm volatile("cp.async.commit_group;" ::: "memory");
    }

    float miA = -INFINITY, miB = -INFINITY, liA = 0.f, liB = 0.f;
    float oa[8][4];
    #pragma unroll
    for (int nt = 0; nt < 8; nt++)
        #pragma unroll
        for (int f = 0; f < 4; f++) oa[nt][f] = 0.f;

    const int NT = S_LEN / 64;
    for (int t = 0; t < NT; t++) {
        if (t < NT - 2) asm volatile("cp.async.wait_group 1;" ::: "memory");
        else            asm volatile("cp.async.wait_group 0;" ::: "memory");
        __syncthreads();
        const uint32_t ksAddr = sbase + (uint32_t)(t & 1) * 18432u + blane;
        const uint32_t vsAddr = ksAddr + 9216u;

        // ---- S = Q K^T : B-frags via ldmatrix.x4 (2 MMAs per LDSM) ---------
        float sa[8][4];
        #pragma unroll
        for (int nt = 0; nt < 8; nt++)
            #pragma unroll
            for (int f = 0; f < 4; f++) sa[nt][f] = 0.f;
        #pragma unroll
        for (int ks = 0; ks < 4; ks++) {
            #pragma unroll
            for (int ntp = 0; ntp < 4; ntp++) {
                uint32_t b4[4];
                ldsm4(b4, ksAddr + (uint32_t)(ntp * 2304 + ks * 32));
                mma_f16(sa[2*ntp    ], qa[ks], &b4[0]);
                mma_f16(sa[2*ntp + 1], qa[ks], &b4[2]);
            }
        }

        // ---- online softmax (exp2 domain) ----------------------------------
        float rmA = -INFINITY, rmB = -INFINITY;
        #pragma unroll
        for (int nt = 0; nt < 8; nt++) {
            rmA = fmaxf(rmA, fmaxf(sa[nt][0], sa[nt][1]));
            rmB = fmaxf(rmB, fmaxf(sa[nt][2], sa[nt][3]));
        }
        rmA = fmaxf(rmA, __shfl_xor_sync(0xffffffffu, rmA, 1));
        rmA = fmaxf(rmA, __shfl_xor_sync(0xffffffffu, rmA, 2));
        rmB = fmaxf(rmB, __shfl_xor_sync(0xffffffffu, rmB, 1));
        rmB = fmaxf(rmB, __shfl_xor_sync(0xffffffffu, rmB, 2));

        const float mAn = fmaxf(miA, rmA);
        const float mBn = fmaxf(miB, rmB);
        const float aA  = exp2f(miA - mAn);
        const float aB  = exp2f(miB - mBn);
        miA = mAn; miB = mBn;

        float rsA = 0.f, rsB = 0.f;
        #pragma unroll
        for (int nt = 0; nt < 8; nt++) {
            sa[nt][0] = exp2f(sa[nt][0] - mAn);
            sa[nt][1] = exp2f(sa[nt][1] - mAn);
            sa[nt][2] = exp2f(sa[nt][2] - mBn);
            sa[nt][3] = exp2f(sa[nt][3] - mBn);
            rsA += sa[nt][0] + sa[nt][1];
            rsB += sa[nt][2] + sa[nt][3];
        }
        rsA += __shfl_xor_sync(0xffffffffu, rsA, 1);
        rsA += __shfl_xor_sync(0xffffffffu, rsA, 2);
        rsB += __shfl_xor_sync(0xffffffffu, rsB, 1);
        rsB += __shfl_xor_sync(0xffffffffu, rsB, 2);
        liA = liA * aA + rsA;
        liB = liB * aB + rsB;
        #pragma unroll
        for (int nt = 0; nt < 8; nt++) {
            oa[nt][0] *= aA; oa[nt][1] *= aA;
            oa[nt][2] *= aB; oa[nt][3] *= aB;
        }

        // ---- O += P V : V B-frags via ldmatrix.x4 --------------------------
        #pragma unroll
        for (int kk = 0; kk < 4; kk++) {
            uint32_t af[4];
            af[0] = h2u(__floats2half2_rn(sa[2*kk  ][0], sa[2*kk  ][1]));
            af[1] = h2u(__floats2half2_rn(sa[2*kk  ][2], sa[2*kk  ][3]));
            af[2] = h2u(__floats2half2_rn(sa[2*kk+1][0], sa[2*kk+1][1]));
            af[3] = h2u(__floats2half2_rn(sa[2*kk+1][2], sa[2*kk+1][3]));
            #pragma unroll
            for (int ntp = 0; ntp < 4; ntp++) {
                uint32_t b4[4];
                ldsm4(b4, vsAddr + (uint32_t)(ntp * 2304 + kk * 32));
                mma_f16(oa[2*ntp    ], af, &b4[0]);
                mma_f16(oa[2*ntp + 1], af, &b4[2]);
            }
        }
        __syncthreads();

        // ---- prefetch tile t+2 ---------------------------------------------
        if (t + 2 < NT) {
            const uint32_t kb = sbase + (uint32_t)(t & 1) * 18432u;
            const uint32_t vb = kb + 9216u;
            const __half* Ksrc = Kb + (size_t)(t + 2) * 64 * 64;
            const __half* Vsrc = Vb + (size_t)(t + 2) * 64;
            #pragma unroll
            for (int i = 0; i < 4; i++) {
                const int fi = tid + i * 256;
                const int half_sel = fi >> 9;
                const int j = fi & 511;
                const int r = j >> 3, seg = j & 7;
                if (half_sel == 0)
                    cp16(kb + (uint32_t)(r * 72 + seg * 8) * 2u, Ksrc + r * 64 + seg * 8);
                else
                    cp16(vb + (uint32_t)(r * 72 + seg * 8) * 2u, Vsrc + (size_t)r * S_LEN + seg * 8);
            }
            asm volatile("cp.async.commit_group;" ::: "memory");
        }
    }

    // ---- epilogue ----------------------------------------------------------
    const int sA = q0 + wid * 16 + gid;
    const int sB = sA + 8;
    const float gA = gate[(size_t)bh * S_LEN + sA];
    const float gB = gate[(size_t)bh * S_LEN + sB];
    const float invA = gA / liA;
    const float invB = gB / liB;
    #pragma unroll
    for (int nt = 0; nt < 8; nt++) {
        const int col = h * 64 + nt * 8 + tig * 2;
        __half2 va = __floats2half2_rn(oa[nt][0] * invA, oa[nt][1] * invA);
        __half2 vb = __floats2half2_rn(oa[nt][2] * invB, oa[nt][3] * invB);
        *(uint32_t*)(ctx + ((size_t)sA * BATCH + b) * EMB + col) = h2u(va);
        *(uint32_t*)(ctx + ((size_t)sB * BATCH + b) * EMB + col) = h2u(vb);
    }
}

// ---------------- fold head_sig into inf2 ---------------------------------
__global__ void combine_sig(const float* __restrict__ hs,
                            const float* __restrict__ w2,
                            const float* __restrict__ b2,
                            float* __restrict__ mcomb,
                            float* __restrict__ cbias)
{
    const int idx = blockIdx.x * blockDim.x + threadIdx.x;
    if (idx < NH * HID) {
        const int h = idx / HID, k = idx % HID;
        float a = 0.f;
        #pragma unroll
        for (int j = 0; j < 64; j++) a += hs[h*64 + j] * w2[j*HID + k];
        mcomb[idx] = a;
    }
    if (idx < NH) {
        float a = 0.f;
        #pragma unroll
        for (int j = 0; j < 64; j++) a += hs[idx*64 + j] * b2[j];
        cbias[idx] = a;
    }
}

// ---------------- head scores + top-12 mask (float4 loads) ----------------
__global__ __launch_bounds__(256)
void head_scores(const float* __restrict__ t1, const float* __restrict__ mcomb,
                 const float* __restrict__ cbias, float* __restrict__ mask)
{
    const int warp = (blockIdx.x * blockDim.x + threadIdx.x) >> 5;
    const int lane = threadIdx.x & 31;
    if (warp >= MROWS) return;
    const float4* row4 = (const float4*)(t1 + (size_t)warp * HID);
    const float4* mc4  = (const float4*)mcomb;

    float acc[NH];
    #pragma unroll
    for (int h = 0; h < NH; h++) acc[h] = 0.f;
    #pragma unroll
    for (int it = 0; it < 4; it++) {
        const int k4 = it * 32 + lane;
        const float4 a = row4[k4];
        #pragma unroll
        for (int h = 0; h < NH; h++) {
            const float4 m = mc4[h * (HID/4) + k4];
            acc[h] += a.x*m.x + a.y*m.y + a.z*m.z + a.w*m.w;
        }
    }
    #pragma unroll
    for (int h = 0; h < NH; h++)
        #pragma unroll
        for (int off = 16; off > 0; off >>= 1)
            acc[h] += __shfl_xor_sync(0xffffffffu, acc[h], off);

    if (lane == 0) {
        float sc[NH], tmp[NH];
        #pragma unroll
        for (int h = 0; h < NH; h++) { sc[h] = acc[h] + cbias[h]; tmp[h] = sc[h]; }
        float thr = 0.f;
        for (int it = 0; it < NH - 4; it++) {
            int bi = 0; float bv = tmp[0];
            #pragma unroll
            for (int h = 1; h < NH; h++) if (tmp[h] > bv) { bv = tmp[h]; bi = h; }
            thr = bv; tmp[bi] = -INFINITY;
        }
        const int s = warp >> 1, b = warp & 1;
        #pragma unroll
        for (int h = 0; h < NH; h++)
            mask[((size_t)(b * NH + h)) * S_LEN + s] = (sc[h] >= thr) ? 1.f : 0.f;
    }
}

// ---------------------------------------------------------------------------
extern "C" void kernel_launch(void* const* d_in, const int* in_sizes, int n_in,
                              void* d_out, int out_size)
{
    const float* query   = (const float*)d_in[0];
    const float* q_w     = (const float*)d_in[1];
    const float* q_b     = (const float*)d_in[2];
    const float* k_w     = (const float*)d_in[3];
    const float* k_b     = (const float*)d_in[4];
    const float* v_w     = (const float*)d_in[5];
    const float* v_b     = (const float*)d_in[6];
    const float* out_w   = (const float*)d_in[7];
    const float* out_b   = (const float*)d_in[8];
    const float* inf1_w  = (const float*)d_in[9];
    const float* inf1_b  = (const float*)d_in[10];
    const float* inf2_w  = (const float*)d_in[11];
    const float* inf2_b  = (const float*)d_in[12];
    const float* head_sig= (const float*)d_in[13];
    float* out = (float*)d_out;

    __half *pqkv, *pctx, *pqh, *pwqkv, *pwo;
    float *pt1, *pmc, *pcb, *pmask;
    cudaGetSymbolAddress((void**)&pqkv, g_qkv);
    cudaGetSymbolAddress((void**)&pctx, g_ctx);
    cudaGetSymbolAddress((void**)&pt1,  g_t1);
    cudaGetSymbolAddress((void**)&pmc,  g_mcomb);
    cudaGetSymbolAddress((void**)&pcb,  g_cbias);
    cudaGetSymbolAddress((void**)&pmask,g_mask);
    cudaGetSymbolAddress((void**)&pqh,  g_qh);
    cudaGetSymbolAddress((void**)&pwqkv,g_wqkv);
    cudaGetSymbolAddress((void**)&pwo,  g_wo);

    const int HGS = 73728;   // fp16 GEMM: 2 stages x 18432 halves
    const int GS3 = 73728;   // 3x-relu fp32 layout
    const int FS  = 36864;   // flash fp16
    cudaFuncSetAttribute(hgemm_qkv, cudaFuncAttributeMaxDynamicSharedMemorySize, HGS);
    cudaFuncSetAttribute(hgemm_out, cudaFuncAttributeMaxDynamicSharedMemorySize, HGS);
    cudaFuncSetAttribute(mgemm_3x_relu, cudaFuncAttributeMaxDynamicSharedMemorySize, GS3);
    cudaFuncSetAttribute(flash_h, cudaFuncAttributeMaxDynamicSharedMemorySize, FS);

    // side stream + fork/join events (created per call; never destroyed so
    // the captured graph's references stay valid)
    cudaStream_t s2;
    cudaEvent_t eFork, eJoin;
    cudaStreamCreateWithFlags(&s2, cudaStreamNonBlocking);
    cudaEventCreateWithFlags(&eFork, cudaEventDisableTiming);
    cudaEventCreateWithFlags(&eJoin, cudaEventDisableTiming);

    cudaEventRecord(eFork, 0);
    cudaStreamWaitEvent(s2, eFork, 0);

    // --- side stream: combine_sig -> 3x MLP -> head_scores -----------------
    combine_sig<<<(NH*HID + 255)/256, 256, 0, s2>>>(head_sig, inf2_w, inf2_b,
                                                    pmc, pcb);
    {
        dim3 g(HID/128, MROWS/128);
        mgemm_3x_relu<<<g, 256, GS3, s2>>>(query, inf1_w, inf1_b, pt1, EMB);
    }
    head_scores<<<MROWS/8, 256, 0, s2>>>(pt1, pmc, pcb, pmask);
    cudaEventRecord(eJoin, s2);

    // --- main stream: fp16 convert -> QKV -----------------------------------
    {
        const int total = NQ4 + 4 * NW4;
        round_all<<<(total + 255)/256, 256>>>(query, q_w, k_w, v_w, out_w,
                                              pqh, pwqkv, pwo);
    }
    {
        dim3 g(EMB/128, MROWS/128, 3);
        hgemm_qkv<<<g, 256, HGS>>>(pqh, pwqkv, q_b, k_b, v_b, pqkv, EMB);
    }

    cudaStreamWaitEvent(0, eJoin, 0);

    // --- flash attention (fp16, ldmatrix) -> ctx fp16 -----------------------
    {
        dim3 g(S_LEN/128, BATCH*NH);
        flash_h<<<g, 256, FS>>>(pqkv, pqkv + HSZ, pqkv + 2*HSZ, pmask, pctx);
    }
    // --- output projection ---------------------------------------------------
    {
        dim3 g(EMB/128, MROWS/128);
        hgemm_out<<<g, 256, HGS>>>(pctx, pwo, out_b, out, EMB);
    }
    (void)in_sizes; (void)n_in; (void)out_size;
}

// round 15
// speedup vs baseline: 1.7264x; 1.0872x over previous
#include <cuda_runtime.h>
#include <cuda_fp16.h>
#include <math.h>
#include <stdint.h>

#define S_LEN 2048
#define BATCH 2
#define EMB   1024
#define NH    16
#define HD    64
#define HID   512
#define MROWS (S_LEN*BATCH)   // 4096
#define HSZ   (BATCH*NH*S_LEN*HD)
#define LOG2E 1.4426950408889634f

// ---------------- scratch (static device globals; no allocation) ----------
__device__ __align__(16) __half g_qkv[3*HSZ];      // q|k fp16 (B,H,S,D); v fp16 (B,H,D,S)
__device__ __align__(16) __half g_ctx[MROWS*EMB];  // (S,B,E) fp16
__device__ float  g_t1 [MROWS*HID];
__device__ float  g_mcomb[NH*HID];
__device__ float  g_cbias[NH];
__device__ float  g_mask[BATCH*NH*S_LEN];
__device__ __align__(16) __half g_qh  [MROWS*EMB]; // fp16 query
__device__ __align__(16) __half g_wqkv[3*EMB*EMB]; // fp16 q_w|k_w|v_w
__device__ __align__(16) __half g_wo  [EMB*EMB];   // fp16 out_w

// =================== helpers ===============================================
__device__ __forceinline__ uint32_t smem_u32(const void* p) {
    uint32_t a;
    asm("{ .reg .u64 t; cvta.to.shared.u64 t, %1; cvt.u32.u64 %0, t; }"
        : "=r"(a) : "l"(p));
    return a;
}
__device__ __forceinline__ void cp16(uint32_t saddr, const void* g) {
    asm volatile("cp.async.cg.shared.global [%0], [%1], 16;"
                 :: "r"(saddr), "l"(g) : "memory");
}
__device__ __forceinline__ void mma_f16(float* d, const uint32_t* a, const uint32_t* b) {
    asm volatile(
        "mma.sync.aligned.m16n8k16.row.col.f32.f16.f16.f32 "
        "{%0,%1,%2,%3}, {%4,%5,%6,%7}, {%8,%9}, {%0,%1,%2,%3};"
        : "+f"(d[0]), "+f"(d[1]), "+f"(d[2]), "+f"(d[3])
        : "r"(a[0]), "r"(a[1]), "r"(a[2]), "r"(a[3]), "r"(b[0]), "r"(b[1]));
}
__device__ __forceinline__ void ldsm4(uint32_t* r, uint32_t addr) {
    asm volatile("ldmatrix.sync.aligned.m8n8.x4.shared.b16 {%0,%1,%2,%3}, [%4];"
                 : "=r"(r[0]), "=r"(r[1]), "=r"(r[2]), "=r"(r[3]) : "r"(addr));
}
__device__ __forceinline__ uint32_t h2u(__half2 h) {
    return *(uint32_t*)&h;
}
// split fp16: x = hi + lo (hi,lo fp16), ~22-bit effective mantissa
__device__ __forceinline__ void split_h2(float x, float y, uint32_t& hi, uint32_t& lo) {
    __half hx = __float2half_rn(x), hy = __float2half_rn(y);
    __half lx = __float2half_rn(x - __half2float(hx));
    __half ly = __float2half_rn(y - __half2float(hy));
    hi = h2u(__halves2half2(hx, hy));
    lo = h2u(__halves2half2(lx, ly));
}

// ---------------- fused fp16 conversion of query + 4 weight matrices ------
#define NQ4 (MROWS*EMB/4)      // 1048576
#define NW4 (EMB*EMB/4)        // 262144 = 1<<18
__global__ void round_all(const float* __restrict__ q,
                          const float* __restrict__ wq,
                          const float* __restrict__ wk,
                          const float* __restrict__ wv,
                          const float* __restrict__ wo,
                          __half* __restrict__ dq,
                          __half* __restrict__ dwqkv,
                          __half* __restrict__ dwo)
{
    const int i = blockIdx.x * blockDim.x + threadIdx.x;
    const float4* src; __half* dst; int off;
    if (i < NQ4) { src = (const float4*)q; dst = dq; off = i; }
    else {
        const int j = i - NQ4;
        const int z = j >> 18;
        off = j & (NW4 - 1);
        if      (z == 0) { src = (const float4*)wq; dst = dwqkv; }
        else if (z == 1) { src = (const float4*)wk; dst = dwqkv + 4*NW4; }
        else if (z == 2) { src = (const float4*)wv; dst = dwqkv + 8*NW4; }
        else             { src = (const float4*)wo; dst = dwo; }
    }
    float4 v = src[off];
    __half2 lo = __floats2half2_rn(v.x, v.y);
    __half2 hi = __floats2half2_rn(v.z, v.w);
    uint2 pk = { h2u(lo), h2u(hi) };
    *(uint2*)(dst + (size_t)off * 4) = pk;
}

// =================== cp.async pipelined fp16 GEMM core =====================
// K-chunks of 64 halves; row pad 72 halves. Stage: A 9216 halves @0, W @9216;
// stage stride 18432 halves (36864 B). 2 stages = 73728 B.
#define HGEMM_BODY(Ag, Wg)                                                     \
    float acc[4][4][4];                                                        \
    _Pragma("unroll")                                                          \
    for (int i = 0; i < 4; i++)                                                \
        _Pragma("unroll")                                                      \
        for (int j = 0; j < 4; j++)                                            \
            _Pragma("unroll")                                                  \
            for (int f = 0; f < 4; f++) acc[i][j][f] = 0.f;                    \
    const int NC = K >> 6;                                                     \
    {                                                                          \
        const uint32_t ab = sbase, wb = sbase + 9216u * 2u;                    \
        _Pragma("unroll")                                                      \
        for (int i = 0; i < 4; i++) {                                          \
            const int fi = tid + i * 256;                                      \
            const int row = fi >> 3, seg = fi & 7;                             \
            const uint32_t off = (uint32_t)(row * 72 + seg * 8) * 2u;          \
            cp16(ab + off, Ag + (size_t)row * K + seg * 8);                    \
            cp16(wb + off, Wg + (size_t)row * K + seg * 8);                    \
        }                                                                      \
        asm volatile("cp.async.commit_group;" ::: "memory");                   \
    }                                                                          \
    for (int c = 0; c < NC; c++) {                                             \
        if (c + 1 < NC) {                                                      \
            const uint32_t st = (uint32_t)((c + 1) & 1) * 18432u * 2u;         \
            const uint32_t ab = sbase + st, wb = sbase + st + 9216u * 2u;      \
            const int kn = (c + 1) << 6;                                       \
            _Pragma("unroll")                                                  \
            for (int i = 0; i < 4; i++) {                                      \
                const int fi = tid + i * 256;                                  \
                const int row = fi >> 3, seg = fi & 7;                         \
                const uint32_t off = (uint32_t)(row * 72 + seg * 8) * 2u;      \
                cp16(ab + off, Ag + (size_t)row * K + kn + seg * 8);           \
                cp16(wb + off, Wg + (size_t)row * K + kn + seg * 8);           \
            }                                                                  \
            asm volatile("cp.async.commit_group;" ::: "memory");               \
            asm volatile("cp.async.wait_group 1;" ::: "memory");               \
        } else {                                                               \
            asm volatile("cp.async.wait_group 0;" ::: "memory");               \
        }                                                                      \
        __syncthreads();                                                       \
        const __half* As = swh + (c & 1) * 18432;                              \
        const __half* Ws = As + 9216;                                          \
        _Pragma("unroll")                                                      \
        for (int ks = 0; ks < 4; ks++) {                                       \
            const int k0 = ks * 16;                                            \
            uint32_t af[4][4];                                                 \
            _Pragma("unroll")                                                  \
            for (int mt = 0; mt < 4; mt++) {                                   \
                const int r = wm * 64 + mt * 16 + gid;                         \
                af[mt][0] = *(const uint32_t*)&As[ r      * 72 + k0 + 2*tig    ];\
                af[mt][1] = *(const uint32_t*)&As[(r + 8) * 72 + k0 + 2*tig    ];\
                af[mt][2] = *(const uint32_t*)&As[ r      * 72 + k0 + 2*tig + 8];\
                af[mt][3] = *(const uint32_t*)&As[(r + 8) * 72 + k0 + 2*tig + 8];\
            }                                                                  \
            uint32_t bf[4][2];                                                 \
            _Pragma("unroll")                                                  \
            for (int nt = 0; nt < 4; nt++) {                                   \
                const int n = wn * 32 + nt * 8 + gid;                          \
                bf[nt][0] = *(const uint32_t*)&Ws[n * 72 + k0 + 2*tig    ];    \
                bf[nt][1] = *(const uint32_t*)&Ws[n * 72 + k0 + 2*tig + 8];    \
            }                                                                  \
            _Pragma("unroll")                                                  \
            for (int mt = 0; mt < 4; mt++)                                     \
                _Pragma("unroll")                                              \
                for (int nt = 0; nt < 4; nt++)                                 \
                    mma_f16(acc[mt][nt], af[mt], bf[nt]);                      \
        }                                                                      \
        __syncthreads();                                                       \
    }

// ---- fused QKV projection: q/k -> (B,H,S,D) fp16; v -> (B,H,D,S) fp16 -----
__global__ __launch_bounds__(256, 2)
void hgemm_qkv(const __half* __restrict__ A, const __half* __restrict__ Wall,
               const float* __restrict__ bq, const float* __restrict__ bk,
               const float* __restrict__ bv, __half* __restrict__ Call, int K)
{
    extern __shared__ __align__(16) char smemraw[];
    __half* swh = (__half*)smemraw;
    const uint32_t sbase = smem_u32(swh);
    const int tid  = threadIdx.x;
    const int wid  = tid >> 5;
    const int lane = tid & 31;
    const int gid  = lane >> 2;
    const int tig  = lane & 3;
    const int wm   = wid >> 2;
    const int wn   = wid & 3;
    const int z    = blockIdx.z;

    const __half* Ag = A + (size_t)blockIdx.y * 128 * K;
    const __half* Wg = Wall + (size_t)z * EMB * EMB + (size_t)blockIdx.x * 128 * K;
    const float* bias = (z == 0) ? bq : (z == 1) ? bk : bv;
    __half* C = Call + (size_t)z * HSZ;
    const float scale = (z == 0) ? 0.125f * LOG2E : 1.f;

    HGEMM_BODY(Ag, Wg)

    if (z < 2) {
        #pragma unroll
        for (int mt = 0; mt < 4; mt++) {
            #pragma unroll
            for (int nt = 0; nt < 4; nt++) {
                const int n = blockIdx.x * 128 + wn * 32 + nt * 8 + tig * 2;
                const float b0 = bias[n], b1 = bias[n + 1];
                #pragma unroll
                for (int half_ = 0; half_ < 2; half_++) {
                    const int m = blockIdx.y * 128 + wm * 64 + mt * 16 + gid + half_ * 8;
                    const float vx = (acc[mt][nt][half_ * 2 + 0] + b0) * scale;
                    const float vy = (acc[mt][nt][half_ * 2 + 1] + b1) * scale;
                    const int s = m >> 1, b = m & 1;
                    const int h = n >> 6, d = n & 63;
                    __half2 hv = __floats2half2_rn(vx, vy);
                    *(uint32_t*)(C + (((size_t)(b * NH + h)) * S_LEN + s) * HD + d) = h2u(hv);
                }
            }
        }
    } else {
        __half* ts = swh;
        #pragma unroll
        for (int mt = 0; mt < 4; mt++) {
            #pragma unroll
            for (int nt = 0; nt < 4; nt++) {
                const int nl = wn * 32 + nt * 8 + tig * 2;
                const int n  = blockIdx.x * 128 + nl;
                const float b0 = bias[n], b1 = bias[n + 1];
                #pragma unroll
                for (int half_ = 0; half_ < 2; half_++) {
                    const int ml = wm * 64 + mt * 16 + gid + half_ * 8;
                    ts[ nl      * 136 + ml] = __float2half_rn(acc[mt][nt][half_ * 2 + 0] + b0);
                    ts[(nl + 1) * 136 + ml] = __float2half_rn(acc[mt][nt][half_ * 2 + 1] + b1);
                }
            }
        }
        __syncthreads();
        #pragma unroll 1
        for (int it = 0; it < 16; it++) {
            const int gr = it * 16 + wid * 2 + (lane >> 4);
            const int nl = gr >> 1, b = gr & 1;
            const int n  = blockIdx.x * 128 + nl;
            const int h  = n >> 6, d = n & 63;
            const int sl = (lane & 15) * 4;
            __half2 p0 = __halves2half2(ts[nl * 136 + 2 * (sl + 0) + b],
                                        ts[nl * 136 + 2 * (sl + 1) + b]);
            __half2 p1 = __halves2half2(ts[nl * 136 + 2 * (sl + 2) + b],
                                        ts[nl * 136 + 2 * (sl + 3) + b]);
            uint2 pk = { h2u(p0), h2u(p1) };
            const int s = blockIdx.y * 64 + sl;
            *(uint2*)(C + (((size_t)(b * NH + h)) * HD + d) * S_LEN + s) = pk;
        }
    }
}

// ---- output projection: ctx fp16 @ wo fp16 -> fp32 out --------------------
__global__ __launch_bounds__(256, 2)
void hgemm_out(const __half* __restrict__ A, const __half* __restrict__ W,
               const float* __restrict__ bias, float* __restrict__ C, int K)
{
    extern __shared__ __align__(16) char smemraw[];
    __half* swh = (__half*)smemraw;
    const uint32_t sbase = smem_u32(swh);
    const int tid  = threadIdx.x;
    const int wid  = tid >> 5;
    const int lane = tid & 31;
    const int gid  = lane >> 2;
    const int tig  = lane & 3;
    const int wm   = wid >> 2;
    const int wn   = wid & 3;

    const __half* Ag = A + (size_t)blockIdx.y * 128 * K;
    const __half* Wg = W + (size_t)blockIdx.x * 128 * K;

    HGEMM_BODY(Ag, Wg)

    #pragma unroll
    for (int mt = 0; mt < 4; mt++) {
        #pragma unroll
        for (int nt = 0; nt < 4; nt++) {
            const int n = blockIdx.x * 128 + wn * 32 + nt * 8 + tig * 2;
            const float b0 = bias[n], b1 = bias[n + 1];
            #pragma unroll
            for (int half_ = 0; half_ < 2; half_++) {
                const int m = blockIdx.y * 128 + wm * 64 + mt * 16 + gid + half_ * 8;
                float2 v;
                v.x = acc[mt][nt][half_ * 2 + 0] + b0;
                v.y = acc[mt][nt][half_ * 2 + 1] + b1;
                *(float2*)(C + (size_t)m * (gridDim.x * 128) + n) = v;
            }
        }
    }
}

// =================== split-fp16 (3xMMA k16) GEMM + ReLU for mask MLP =======
// fp32 inputs via cp.async (stride-36 fp32 rows); in-register hi/lo split.
// Effective ~22-bit mantissa -> top-k flip-safe like split-tf32, ~2x faster.
__global__ __launch_bounds__(256)
void hgemm_3x_relu(const float* __restrict__ A, const float* __restrict__ W,
                   const float* __restrict__ bias, float* __restrict__ C, int K)
{
    extern __shared__ __align__(16) char smemraw[];
    uint32_t* sw = (uint32_t*)smemraw;
    const uint32_t sbase = smem_u32(sw);
    const float* swf = (const float*)sw;
    const int tid  = threadIdx.x;
    const int wid  = tid >> 5;
    const int lane = tid & 31;
    const int gid  = lane >> 2;
    const int tig  = lane & 3;
    const int wm   = wid >> 2;
    const int wn   = wid & 3;

    const float* Ag = A + (size_t)blockIdx.y * 128 * K;
    const float* Wg = W + (size_t)blockIdx.x * 128 * K;

    float acc[4][4][4];
    #pragma unroll
    for (int i = 0; i < 4; i++)
        #pragma unroll
        for (int j = 0; j < 4; j++)
            #pragma unroll
            for (int f = 0; f < 4; f++) acc[i][j][f] = 0.f;

    const int NC = K >> 5;
    const int r0 = tid >> 3;
    const int sg = tid & 7;

    {
        const uint32_t ab = sbase, wb = sbase + 4608u * 4u;
        #pragma unroll
        for (int i = 0; i < 4; i++) {
            const int row = r0 + i * 32;
            const uint32_t off = (uint32_t)(row * 36 + sg * 4) * 4u;
            cp16(ab + off, Ag + (size_t)row * K + sg * 4);
            cp16(wb + off, Wg + (size_t)row * K + sg * 4);
        }
        asm volatile("cp.async.commit_group;" ::: "memory");
    }

    for (int c = 0; c < NC; c++) {
        if (c + 1 < NC) {
            const uint32_t st = (uint32_t)((c + 1) & 1) * 9216u * 4u;
            const uint32_t ab = sbase + st, wb = sbase + st + 4608u * 4u;
            const int kn = (c + 1) << 5;
            #pragma unroll
            for (int i = 0; i < 4; i++) {
                const int row = r0 + i * 32;
                const uint32_t off = (uint32_t)(row * 36 + sg * 4) * 4u;
                cp16(ab + off, Ag + (size_t)row * K + kn + sg * 4);
                cp16(wb + off, Wg + (size_t)row * K + kn + sg * 4);
            }
            asm volatile("cp.async.commit_group;" ::: "memory");
            asm volatile("cp.async.wait_group 1;" ::: "memory");
        } else {
            asm volatile("cp.async.wait_group 0;" ::: "memory");
        }
        __syncthreads();

        const float* As = swf + (c & 1) * 9216;
        const float* Ws = As + 4608;
        #pragma unroll
        for (int ks = 0; ks < 2; ks++) {        // two k16 steps per 32-float chunk
            const int k0 = ks * 16;
            uint32_t ah[4][4], al[4][4];
            #pragma unroll
            for (int mt = 0; mt < 4; mt++) {
                const int r = wm * 64 + mt * 16 + gid;
                float2 p0 = *(const float2*)&As[ r      * 36 + k0 + 2*tig    ];
                float2 p1 = *(const float2*)&As[(r + 8) * 36 + k0 + 2*tig    ];
                float2 p2 = *(const float2*)&As[ r      * 36 + k0 + 2*tig + 8];
                float2 p3 = *(const float2*)&As[(r + 8) * 36 + k0 + 2*tig + 8];
                split_h2(p0.x, p0.y, ah[mt][0], al[mt][0]);
                split_h2(p1.x, p1.y, ah[mt][1], al[mt][1]);
                split_h2(p2.x, p2.y, ah[mt][2], al[mt][2]);
                split_h2(p3.x, p3.y, ah[mt][3], al[mt][3]);
            }
            uint32_t bh_[4][2], bl_[4][2];
            #pragma unroll
            for (int nt = 0; nt < 4; nt++) {
                const int n = wn * 32 + nt * 8 + gid;
                float2 q0 = *(const float2*)&Ws[n * 36 + k0 + 2*tig    ];
                float2 q1 = *(const float2*)&Ws[n * 36 + k0 + 2*tig + 8];
                split_h2(q0.x, q0.y, bh_[nt][0], bl_[nt][0]);
                split_h2(q1.x, q1.y, bh_[nt][1], bl_[nt][1]);
            }
            #pragma unroll
            for (int mt = 0; mt < 4; mt++)
                #pragma unroll
                for (int nt = 0; nt < 4; nt++) {
                    mma_f16(acc[mt][nt], al[mt], bh_[nt]);
                    mma_f16(acc[mt][nt], ah[mt], bl_[nt]);
                    mma_f16(acc[mt][nt], ah[mt], bh_[nt]);
                }
        }
        __syncthreads();
    }

    #pragma unroll
    for (int mt = 0; mt < 4; mt++) {
        #pragma unroll
        for (int nt = 0; nt < 4; nt++) {
            const int n = blockIdx.x * 128 + wn * 32 + nt * 8 + tig * 2;
            const float b0 = bias[n], b1 = bias[n + 1];
            #pragma unroll
            for (int half_ = 0; half_ < 2; half_++) {
                const int m = blockIdx.y * 128 + wm * 64 + mt * 16 + gid + half_ * 8;
                float2 v;
                v.x = fmaxf(acc[mt][nt][half_ * 2 + 0] + b0, 0.f);
                v.y = fmaxf(acc[mt][nt][half_ * 2 + 1] + b1, 0.f);
                *(float2*)(C + (size_t)m * (gridDim.x * 128) + n) = v;
            }
        }
    }
}

// =================== fp16 flash attention with ldmatrix (R14) ==============
__global__ __launch_bounds__(256, 2)
void flash_h(const __half* __restrict__ Q, const __half* __restrict__ Kg,
             const __half* __restrict__ Vg, const float* __restrict__ gate,
             __half* __restrict__ ctx)
{
    extern __shared__ __align__(16) char smemraw[];
    __half* swh = (__half*)smemraw;
    const uint32_t sbase = smem_u32(swh);
    const int tid  = threadIdx.x;
    const int wid  = tid >> 5;
    const int lane = tid & 31;
    const int gid  = lane >> 2;
    const int tig  = lane & 3;
    const int bh   = blockIdx.y;
    const int b    = bh >> 4, h = bh & 15;
    const int q0   = blockIdx.x * 128;

    const __half* Qt = Q  + ((size_t)bh * S_LEN + q0) * HD;
    const __half* Kb = Kg + (size_t)bh * S_LEN * HD;
    const __half* Vb = Vg + (size_t)bh * HD * S_LEN;

    const int a23 = lane >> 3, rin = lane & 7;
    const uint32_t alane = (uint32_t)((((a23 & 1) * 8 + rin) * 72 + (a23 >> 1) * 8) * 2);
    const uint32_t blane = (uint32_t)((((a23 >> 1) * 8 + rin) * 72 + (a23 & 1) * 8) * 2);

    #pragma unroll
    for (int i = 0; i < 4; i++) {
        const int fi = tid + i * 256;
        const int r = fi >> 3, seg = fi & 7;
        uint4 v = *(const uint4*)(Qt + r * 64 + seg * 8);
        *(uint4*)(swh + r * 72 + seg * 8) = v;
    }
    __syncthreads();
    uint32_t qa[4][4];
    {
        const uint32_t qaddr = sbase + (uint32_t)(wid * 16) * 144u + alane;
        #pragma unroll
        for (int ks = 0; ks < 4; ks++)
            ldsm4(qa[ks], qaddr + (uint32_t)(ks * 32));
    }
    __syncthreads();

    #pragma unroll 1
    for (int t = 0; t < 2; t++) {
        const uint32_t kb = sbase + (uint32_t)t * 18432u;
        const uint32_t vb = kb + 9216u;
        const __half* Ksrc = Kb + (size_t)t * 64 * 64;
        const __half* Vsrc = Vb + (size_t)t * 64;
        #pragma unroll
        for (int i = 0; i < 4; i++) {
            const int fi = tid + i * 256;
            const int half_sel = fi >> 9;
            const int j = fi & 511;
            const int r = j >> 3, seg = j & 7;
            if (half_sel == 0)
                cp16(kb + (uint32_t)(r * 72 + seg * 8) * 2u, Ksrc + r * 64 + seg * 8);
            else
                cp16(vb + (uint32_t)(r * 72 + seg * 8) * 2u, Vsrc + (size_t)r * S_LEN + seg * 8);
        }
        asm volatile("cp.async.commit_group;" ::: "memory");
    }

    float miA = -INFINITY, miB = -INFINITY, liA = 0.f, liB = 0.f;
    float oa[8][4];
    #pragma unroll
    for (int nt = 0; nt < 8; nt++)
        #pragma unroll
        for (int f = 0; f < 4; f++) oa[nt][f] = 0.f;

    const int NT = S_LEN / 64;
    for (int t = 0; t < NT; t++) {
        if (t < NT - 2) asm volatile("cp.async.wait_group 1;" ::: "memory");
        else            asm volatile("cp.async.wait_group 0;" ::: "memory");
        __syncthreads();
        const uint32_t ksAddr = sbase + (uint32_t)(t & 1) * 18432u + blane;
        const uint32_t vsAddr = ksAddr + 9216u;

        float sa[8][4];
        #pragma unroll
        for (int nt = 0; nt < 8; nt++)
            #pragma unroll
            for (int f = 0; f < 4; f++) sa[nt][f] = 0.f;
        #pragma unroll
        for (int ks = 0; ks < 4; ks++) {
            #pragma unroll
            for (int ntp = 0; ntp < 4; ntp++) {
                uint32_t b4[4];
                ldsm4(b4, ksAddr + (uint32_t)(ntp * 2304 + ks * 32));
                mma_f16(sa[2*ntp    ], qa[ks], &b4[0]);
                mma_f16(sa[2*ntp + 1], qa[ks], &b4[2]);
            }
        }

        float rmA = -INFINITY, rmB = -INFINITY;
        #pragma unroll
        for (int nt = 0; nt < 8; nt++) {
            rmA = fmaxf(rmA, fmaxf(sa[nt][0], sa[nt][1]));
            rmB = fmaxf(rmB, fmaxf(sa[nt][2], sa[nt][3]));
        }
        rmA = fmaxf(rmA, __shfl_xor_sync(0xffffffffu, rmA, 1));
        rmA = fmaxf(rmA, __shfl_xor_sync(0xffffffffu, rmA, 2));
        rmB = fmaxf(rmB, __shfl_xor_sync(0xffffffffu, rmB, 1));
        rmB = fmaxf(rmB, __shfl_xor_sync(0xffffffffu, rmB, 2));

        const float mAn = fmaxf(miA, rmA);
        const float mBn = fmaxf(miB, rmB);
        const float aA  = exp2f(miA - mAn);
        const float aB  = exp2f(miB - mBn);
        miA = mAn; miB = mBn;

        float rsA = 0.f, rsB = 0.f;
        #pragma unroll
        for (int nt = 0; nt < 8; nt++) {
            sa[nt][0] = exp2f(sa[nt][0] - mAn);
            sa[nt][1] = exp2f(sa[nt][1] - mAn);
            sa[nt][2] = exp2f(sa[nt][2] - mBn);
            sa[nt][3] = exp2f(sa[nt][3] - mBn);
            rsA += sa[nt][0] + sa[nt][1];
            rsB += sa[nt][2] + sa[nt][3];
        }
        rsA += __shfl_xor_sync(0xffffffffu, rsA, 1);
        rsA += __shfl_xor_sync(0xffffffffu, rsA, 2);
        rsB += __shfl_xor_sync(0xffffffffu, rsB, 1);
        rsB += __shfl_xor_sync(0xffffffffu, rsB, 2);
        liA = liA * aA + rsA;
        liB = liB * aB + rsB;
        #pragma unroll
        for (int nt = 0; nt < 8; nt++) {
            oa[nt][0] *= aA; oa[nt][1] *= aA;
            oa[nt][2] *= aB; oa[nt][3] *= aB;
        }

        #pragma unroll
        for (int kk = 0; kk < 4; kk++) {
            uint32_t af[4];
            af[0] = h2u(__floats2half2_rn(sa[2*kk  ][0], sa[2*kk  ][1]));
            af[1] = h2u(__floats2half2_rn(sa[2*kk  ][2], sa[2*kk  ][3]));
            af[2] = h2u(__floats2half2_rn(sa[2*kk+1][0], sa[2*kk+1][1]));
            af[3] = h2u(__floats2half2_rn(sa[2*kk+1][2], sa[2*kk+1][3]));
            #pragma unroll
            for (int ntp = 0; ntp < 4; ntp++) {
                uint32_t b4[4];
                ldsm4(b4, vsAddr + (uint32_t)(ntp * 2304 + kk * 32));
                mma_f16(oa[2*ntp    ], af, &b4[0]);
                mma_f16(oa[2*ntp + 1], af, &b4[2]);
            }
        }
        __syncthreads();

        if (t + 2 < NT) {
            const uint32_t kb = sbase + (uint32_t)(t & 1) * 18432u;
            const uint32_t vb = kb + 9216u;
            const __half* Ksrc = Kb + (size_t)(t + 2) * 64 * 64;
            const __half* Vsrc = Vb + (size_t)(t + 2) * 64;
            #pragma unroll
            for (int i = 0; i < 4; i++) {
                const int fi = tid + i * 256;
                const int half_sel = fi >> 9;
                const int j = fi & 511;
                const int r = j >> 3, seg = j & 7;
                if (half_sel == 0)
                    cp16(kb + (uint32_t)(r * 72 + seg * 8) * 2u, Ksrc + r * 64 + seg * 8);
                else
                    cp16(vb + (uint32_t)(r * 72 + seg * 8) * 2u, Vsrc + (size_t)r * S_LEN + seg * 8);
            }
            asm volatile("cp.async.commit_group;" ::: "memory");
        }
    }

    const int sA = q0 + wid * 16 + gid;
    const int sB = sA + 8;
    const float gA = gate[(size_t)bh * S_LEN + sA];
    const float gB = gate[(size_t)bh * S_LEN + sB];
    const float invA = gA / liA;
    const float invB = gB / liB;
    #pragma unroll
    for (int nt = 0; nt < 8; nt++) {
        const int col = h * 64 + nt * 8 + tig * 2;
        __half2 va = __floats2half2_rn(oa[nt][0] * invA, oa[nt][1] * invA);
        __half2 vb = __floats2half2_rn(oa[nt][2] * invB, oa[nt][3] * invB);
        *(uint32_t*)(ctx + ((size_t)sA * BATCH + b) * EMB + col) = h2u(va);
        *(uint32_t*)(ctx + ((size_t)sB * BATCH + b) * EMB + col) = h2u(vb);
    }
}

// ---------------- fold head_sig into inf2 ---------------------------------
__global__ void combine_sig(const float* __restrict__ hs,
                            const float* __restrict__ w2,
                            const float* __restrict__ b2,
                            float* __restrict__ mcomb,
                            float* __restrict__ cbias)
{
    const int idx = blockIdx.x * blockDim.x + threadIdx.x;
    if (idx < NH * HID) {
        const int h = idx / HID, k = idx % HID;
        float a = 0.f;
        #pragma unroll
        for (int j = 0; j < 64; j++) a += hs[h*64 + j] * w2[j*HID + k];
        mcomb[idx] = a;
    }
    if (idx < NH) {
        float a = 0.f;
        #pragma unroll
        for (int j = 0; j < 64; j++) a += hs[idx*64 + j] * b2[j];
        cbias[idx] = a;
    }
}

// ---------------- head scores + top-12 mask (float4 loads) ----------------
__global__ __launch_bounds__(256)
void head_scores(const float* __restrict__ t1, const float* __restrict__ mcomb,
                 const float* __restrict__ cbias, float* __restrict__ mask)
{
    const int warp = (blockIdx.x * blockDim.x + threadIdx.x) >> 5;
    const int lane = threadIdx.x & 31;
    if (warp >= MROWS) return;
    const float4* row4 = (const float4*)(t1 + (size_t)warp * HID);
    const float4* mc4  = (const float4*)mcomb;

    float acc[NH];
    #pragma unroll
    for (int h = 0; h < NH; h++) acc[h] = 0.f;
    #pragma unroll
    for (int it = 0; it < 4; it++) {
        const int k4 = it * 32 + lane;
        const float4 a = row4[k4];
        #pragma unroll
        for (int h = 0; h < NH; h++) {
            const float4 m = mc4[h * (HID/4) + k4];
            acc[h] += a.x*m.x + a.y*m.y + a.z*m.z + a.w*m.w;
        }
    }
    #pragma unroll
    for (int h = 0; h < NH; h++)
        #pragma unroll
        for (int off = 16; off > 0; off >>= 1)
            acc[h] += __shfl_xor_sync(0xffffffffu, acc[h], off);

    if (lane == 0) {
        float sc[NH], tmp[NH];
        #pragma unroll
        for (int h = 0; h < NH; h++) { sc[h] = acc[h] + cbias[h]; tmp[h] = sc[h]; }
        float thr = 0.f;
        for (int it = 0; it < NH - 4; it++) {
            int bi = 0; float bv = tmp[0];
            #pragma unroll
            for (int h = 1; h < NH; h++) if (tmp[h] > bv) { bv = tmp[h]; bi = h; }
            thr = bv; tmp[bi] = -INFINITY;
        }
        const int s = warp >> 1, b = warp & 1;
        #pragma unroll
        for (int h = 0; h < NH; h++)
            mask[((size_t)(b * NH + h)) * S_LEN + s] = (sc[h] >= thr) ? 1.f : 0.f;
    }
}

// ---------------------------------------------------------------------------
extern "C" void kernel_launch(void* const* d_in, const int* in_sizes, int n_in,
                              void* d_out, int out_size)
{
    const float* query   = (const float*)d_in[0];
    const float* q_w     = (const float*)d_in[1];
    const float* q_b     = (const float*)d_in[2];
    const float* k_w     = (const float*)d_in[3];
    const float* k_b     = (const float*)d_in[4];
    const float* v_w     = (const float*)d_in[5];
    const float* v_b     = (const float*)d_in[6];
    const float* out_w   = (const float*)d_in[7];
    const float* out_b   = (const float*)d_in[8];
    const float* inf1_w  = (const float*)d_in[9];
    const float* inf1_b  = (const float*)d_in[10];
    const float* inf2_w  = (const float*)d_in[11];
    const float* inf2_b  = (const float*)d_in[12];
    const float* head_sig= (const float*)d_in[13];
    float* out = (float*)d_out;

    __half *pqkv, *pctx, *pqh, *pwqkv, *pwo;
    float *pt1, *pmc, *pcb, *pmask;
    cudaGetSymbolAddress((void**)&pqkv, g_qkv);
    cudaGetSymbolAddress((void**)&pctx, g_ctx);
    cudaGetSymbolAddress((void**)&pt1,  g_t1);
    cudaGetSymbolAddress((void**)&pmc,  g_mcomb);
    cudaGetSymbolAddress((void**)&pcb,  g_cbias);
    cudaGetSymbolAddress((void**)&pmask,g_mask);
    cudaGetSymbolAddress((void**)&pqh,  g_qh);
    cudaGetSymbolAddress((void**)&pwqkv,g_wqkv);
    cudaGetSymbolAddress((void**)&pwo,  g_wo);

    const int HGS = 73728;   // fp16 GEMM: 2 stages x 18432 halves
    const int GS3 = 73728;   // mask MLP fp32 stage layout
    const int FS  = 36864;   // flash fp16
    cudaFuncSetAttribute(hgemm_qkv, cudaFuncAttributeMaxDynamicSharedMemorySize, HGS);
    cudaFuncSetAttribute(hgemm_out, cudaFuncAttributeMaxDynamicSharedMemorySize, HGS);
    cudaFuncSetAttribute(hgemm_3x_relu, cudaFuncAttributeMaxDynamicSharedMemorySize, GS3);
    cudaFuncSetAttribute(flash_h, cudaFuncAttributeMaxDynamicSharedMemorySize, FS);

    // side stream + fork/join events (created per call; never destroyed so
    // the captured graph's references stay valid)
    cudaStream_t s2;
    cudaEvent_t eFork, eJoin;
    cudaStreamCreateWithFlags(&s2, cudaStreamNonBlocking);
    cudaEventCreateWithFlags(&eFork, cudaEventDisableTiming);
    cudaEventCreateWithFlags(&eJoin, cudaEventDisableTiming);

    cudaEventRecord(eFork, 0);
    cudaStreamWaitEvent(s2, eFork, 0);

    // --- side stream: combine_sig -> split-fp16 MLP -> head_scores ---------
    combine_sig<<<(NH*HID + 255)/256, 256, 0, s2>>>(head_sig, inf2_w, inf2_b,
                                                    pmc, pcb);
    {
        dim3 g(HID/128, MROWS/128);
        hgemm_3x_relu<<<g, 256, GS3, s2>>>(query, inf1_w, inf1_b, pt1, EMB);
    }
    head_scores<<<MROWS/8, 256, 0, s2>>>(pt1, pmc, pcb, pmask);
    cudaEventRecord(eJoin, s2);

    // --- main stream: fp16 convert -> QKV -----------------------------------
    {
        const int total = NQ4 + 4 * NW4;
        round_all<<<(total + 255)/256, 256>>>(query, q_w, k_w, v_w, out_w,
                                              pqh, pwqkv, pwo);
    }
    {
        dim3 g(EMB/128, MROWS/128, 3);
        hgemm_qkv<<<g, 256, HGS>>>(pqh, pwqkv, q_b, k_b, v_b, pqkv, EMB);
    }

    cudaStreamWaitEvent(0, eJoin, 0);

    // --- flash attention (fp16, ldmatrix) -> ctx fp16 -----------------------
    {
        dim3 g(S_LEN/128, BATCH*NH);
        flash_h<<<g, 256, FS>>>(pqkv, pqkv + HSZ, pqkv + 2*HSZ, pmask, pctx);
    }
    // --- output projection ---------------------------------------------------
    {
        dim3 g(EMB/128, MROWS/128);
        hgemm_out<<<g, 256, HGS>>>(pctx, pwo, out_b, out, EMB);
    }
    (void)in_sizes; (void)n_in; (void)out_size;
}